// round 2
// baseline (speedup 1.0000x reference)
#include <cuda_runtime.h>
#include <math.h>

#define NN      1024
#define KNN     8
#define D_IN    36
#define NPAIR   (NN*(NN-1)/2)    // 523776
#define EPSV    1e-5f
#define SLOPE   0.01f

// ---------------- device scratch (no allocations allowed) ----------------
__device__ float g_node[NN*100];          // [x(36) | e1(32) | e2(32)] per node
__device__ float g_mean[D_IN], g_scale[D_IN];
__device__ float4 g_xy[NN];               // compact first-4 normalized feats
__device__ int   g_idx[NN*KNN];
__device__ float g_w1t1[288*32];          // ec1_w1 transposed  [t][o]
__device__ float g_w1t2[256*32];          // ec2_w1 transposed  [t][o]
__device__ float g_m1[100], g_s1[100], g_m2[100], g_s2[100];
__device__ float g_W1p[200*32];           // BN-scaled l_w1, layout [f][o]
__device__ float g_c[32];                 // folded bias for first pair layer
__device__ float g_A[NN*32];
__device__ float g_B[NN*32];
__device__ unsigned int g_bar;            // grid-sync ticket counter (monotonic)

__device__ __forceinline__ float leaky(float x){ return fmaxf(x, SLOPE*x); }
__device__ __forceinline__ int rowstart(int i){ return i*NN - ((i*(i+1))>>1); }

// software grid barrier: all blocks must be co-resident (grid<=148, 1 CTA/SM)
__device__ __forceinline__ void gridsync(unsigned int nblk){
    __threadfence();                 // release: make this thread's writes visible
    __syncthreads();
    if (threadIdx.x == 0){
        unsigned int t = atomicAdd(&g_bar, 1u);
        unsigned int target = t - (t % nblk) + nblk;
        volatile unsigned int* vb = &g_bar;
        while (*vb < target) {}
        __threadfence();             // acquire
    }
    __syncthreads();
}

// ---------------- 1) BN stats (blocks 0..35) + weight transpose (36..71) ----
__global__ void k_statsT(const float* __restrict__ feat,
                         const float* __restrict__ w1, const float* __restrict__ w2){
    if (blockIdx.x < 36){
        int f = blockIdx.x;
        __shared__ float ss[256], sq[256];
        float s=0.f, q=0.f;
        for(int i=threadIdx.x;i<NN;i+=256){ float v=feat[i*D_IN+f]; s+=v; q+=v*v; }
        ss[threadIdx.x]=s; sq[threadIdx.x]=q; __syncthreads();
        for(int o=128;o>0;o>>=1){
            if(threadIdx.x<o){ ss[threadIdx.x]+=ss[threadIdx.x+o]; sq[threadIdx.x]+=sq[threadIdx.x+o]; }
            __syncthreads();
        }
        if(threadIdx.x==0){
            float m=ss[0]*(1.f/NN);
            float var=sq[0]*(1.f/NN)-m*m;
            g_mean[f]=m; g_scale[f]=rsqrtf(var+EPSV);
        }
    } else {
        int t = (blockIdx.x-36)*256 + threadIdx.x;
        if (t < 288*32){ int r=t>>5, o=t&31; g_w1t1[t] = w1[o*288+r]; }
        if (t < 256*32){ int r=t>>5, o=t&31; g_w1t2[t] = w2[o*256+r]; }
    }
}

// ---------------- 2) normalize x into g_node; emit cells + compact coords ----
__global__ void k_norm(const float* __restrict__ feat, const float* __restrict__ bng,
                       const float* __restrict__ bnb, float* __restrict__ out_cells){
    int t = blockIdx.x*blockDim.x + threadIdx.x;
    if (t < NN*D_IN){
        int i=t/D_IN, f=t%D_IN;
        float v = (feat[t]-g_mean[f])*g_scale[f]*bng[f]+bnb[f];
        g_node[i*100+f] = v;
        if (f < 4) ((float*)g_xy)[i*4+f] = v;
    }
    if (t < NN*5){
        int i=t/5, c=t%5;
        out_cells[i*5+c] = feat[i*D_IN+c];
    }
}

// ---------------- 3) kNN via shared coords + early-reject insertion ----------
__global__ void __launch_bounds__(256) k_knn(){
    __shared__ float4 sxy[NN];       // 16 KB
    for(int t=threadIdx.x; t<NN; t+=256) sxy[t] = g_xy[t];
    __syncthreads();

    int w = threadIdx.x>>5, lane = threadIdx.x&31;
    int node = blockIdx.x*8 + w;
    const float4 xi = sxy[node];

    float d8[8]; int id8[8];
#pragma unroll
    for(int k=0;k<8;k++){ d8[k]=3.4e38f; id8[k]=0x7fffffff; }
    float kth = 3.4e38f; int kthi = 0x7fffffff;

    for(int it=0; it<NN/32; it++){
        int j = lane + it*32;
        float4 xj = sxy[j];
        float cd = fabsf(xi.x-xj.x)+fabsf(xi.y-xj.y)+fabsf(xi.z-xj.z)+fabsf(xi.w-xj.w);
        int ci = j;
        if (cd < kth || (cd==kth && ci < kthi)){
#pragma unroll
            for(int k=0;k<8;k++){
                bool sw = (cd < d8[k]) || (cd==d8[k] && ci < id8[k]);
                float td = sw ? d8[k] : cd; int ti = sw ? id8[k] : ci;
                d8[k]  = sw ? cd : d8[k]; id8[k] = sw ? ci : id8[k];
                cd=td; ci=ti;
            }
            kth = d8[7]; kthi = id8[7];
        }
    }
    // merge 32 sorted-8 lists: 8 rounds of warp argmin on (d, idx)
    for(int r=0;r<8;r++){
        float bd=d8[0]; int bi=id8[0];
#pragma unroll
        for(int off=16;off>0;off>>=1){
            float od=__shfl_xor_sync(0xffffffffu,bd,off);
            int   oi=__shfl_xor_sync(0xffffffffu,bi,off);
            if (od<bd || (od==bd && oi<bi)){ bd=od; bi=oi; }
        }
        if (lane==0) g_idx[node*KNN+r]=bi;
        if (id8[0]==bi){
#pragma unroll
            for(int k=0;k<7;k++){ d8[k]=d8[k+1]; id8[k]=id8[k+1]; }
            d8[7]=3.4e38f; id8[7]=0x7fffffff;
        }
    }
}

// ---------------- 4) edge conv 1 ----------------
__global__ void __launch_bounds__(256) k_edge1(const float* __restrict__ b1,
                        const float* __restrict__ w2, const float* __restrict__ b2){
    __shared__ float sv[8][288];
    __shared__ float sh[8][32];
    int w = threadIdx.x>>5, lane = threadIdx.x&31;
    int node = blockIdx.x*8 + w;
    for(int t=lane;t<288;t+=32){
        int f=t>>3, k=t&7;
        sv[w][t] = g_node[g_idx[node*KNN+k]*100 + f];
    }
    __syncwarp();
    float acc = b1[lane];
    for(int t=0;t<288;t++) acc += g_w1t1[t*32+lane]*sv[w][t];
    sh[w][lane]=leaky(acc);
    __syncwarp();
    float acc2 = b2[lane];
#pragma unroll
    for(int f=0;f<32;f++) acc2 += w2[lane*32+f]*sh[w][f];
    g_node[node*100+36+lane]=leaky(acc2);
}

// ---------------- 5) fused tail: edge2 -> pstats -> w1p -> ab (grid-synced) ----
#define TAILBLK 128
__global__ void __launch_bounds__(256) k_tail(
        const float* __restrict__ b1, const float* __restrict__ w2,
        const float* __restrict__ b2,
        const float* __restrict__ lw1, const float* __restrict__ lb1,
        const float* __restrict__ lbng, const float* __restrict__ lbnb){
    __shared__ float smem[8*288 + 8*32];   // big enough for every phase
    int w = threadIdx.x>>5, lane = threadIdx.x&31;

    // ---- phase A: edge conv 2 ----
    {
        float (*sv)[256] = (float(*)[256])smem;
        float (*sh)[32]  = (float(*)[32])(smem + 8*256);
        int node = blockIdx.x*8 + w;
        for(int t=lane;t<256;t+=32){
            int f=t>>3, k=t&7;
            sv[w][t] = g_node[g_idx[node*KNN+k]*100 + 36 + f];
        }
        __syncwarp();
        float acc = b1[lane];
        for(int t=0;t<256;t++) acc += g_w1t2[t*32+lane]*sv[w][t];
        sh[w][lane]=leaky(acc);
        __syncwarp();
        float acc2 = b2[lane];
#pragma unroll
        for(int f=0;f<32;f++) acc2 += w2[lane*32+f]*sh[w][f];
        g_node[node*100+68+lane]=leaky(acc2);
    }
    gridsync(TAILBLK);

    // ---- phase B: pair-BN stats via weighted node moments (blocks 0..99) ----
    if (blockIdx.x < 100){
        int f = blockIdx.x;
        float (*s)[256] = (float(*)[256])smem;
        float sa=0,qa=0,sb=0,qb=0;
        for(int i=threadIdx.x;i<NN;i+=256){
            float v=__ldcg(&g_node[i*100+f]);
            float wa=(float)(NN-1-i), wb=(float)i;
            sa+=wa*v; qa+=wa*v*v; sb+=wb*v; qb+=wb*v*v;
        }
        s[0][threadIdx.x]=sa; s[1][threadIdx.x]=qa; s[2][threadIdx.x]=sb; s[3][threadIdx.x]=qb;
        __syncthreads();
        for(int o=128;o>0;o>>=1){
            if(threadIdx.x<o){
#pragma unroll
                for(int c=0;c<4;c++) s[c][threadIdx.x]+=s[c][threadIdx.x+o];
            }
            __syncthreads();
        }
        if(threadIdx.x==0){
            const float invP = 1.0f/(float)NPAIR;
            float m1=s[0][0]*invP, q1=s[1][0]*invP;
            float m2=s[2][0]*invP, q2=s[3][0]*invP;
            g_m1[f]=m1; g_s1[f]=rsqrtf(q1-m1*m1+EPSV);
            g_m2[f]=m2; g_s2[f]=rsqrtf(q2-m2*m2+EPSV);
        }
    } else {
        __syncthreads(); // keep barrier participation symmetric inside block
    }
    gridsync(TAILBLK);

    // ---- phase C: fold BN into W1 (distributed) + folded bias (block 0) ----
    for(int t=blockIdx.x*256+threadIdx.x; t<6400; t+=TAILBLK*256){
        int o=t&31, f=t>>5;
        float sc = (f<100)? lbng[f]*__ldcg(&g_s1[f]) : lbng[f]*__ldcg(&g_s2[f-100]);
        g_W1p[t] = lw1[o*200+f]*sc;
    }
    if (blockIdx.x==0 && threadIdx.x<32){
        int o=threadIdx.x;
        float c=lb1[o];
        for(int f=0;f<200;f++){
            float m  = (f<100)? __ldcg(&g_m1[f]) : __ldcg(&g_m2[f-100]);
            float sc = (f<100)? lbng[f]*__ldcg(&g_s1[f]) : lbng[f]*__ldcg(&g_s2[f-100]);
            c += lw1[o*200+f]*(lbnb[f]-m*sc);
        }
        g_c[o]=c;
    }
    gridsync(TAILBLK);

    // ---- phase D: per-node projections A (with c folded) and B ----
    {
        float (*srow)[100] = (float(*)[100])smem;
        int node = blockIdx.x*8+w;
        for(int f=lane;f<100;f+=32) srow[w][f]=__ldcg(&g_node[node*100+f]);
        __syncwarp();
        float a=__ldcg(&g_c[lane]), b=0.f;
        for(int f=0;f<100;f++){
            float v=srow[w][f];
            a += v*__ldcg(&g_W1p[f*32+lane]);
            b += v*__ldcg(&g_W1p[(100+f)*32+lane]);
        }
        g_A[node*32+lane]=a;
        g_B[node*32+lane]=b;
    }
}

// ---------------- 6) the big pair kernel: 2 pairs/thread ----------------
__global__ void __launch_bounds__(256) k_pairs(const float* __restrict__ lw2,
                                               const float* __restrict__ lb2,
                                               const float* __restrict__ lw3,
                                               const float* __restrict__ lb3,
                                               float* __restrict__ out){
    __shared__ float sW2[1024], sb2[32], sW3[64], sb3[2];
    for(int t=threadIdx.x;t<1024;t+=256) sW2[t]=lw2[t];
    if(threadIdx.x<32) sb2[threadIdx.x]=lb2[threadIdx.x];
    if(threadIdx.x<64) sW3[threadIdx.x]=lw3[threadIdx.x];
    if(threadIdx.x<2)  sb3[threadIdx.x]=lb3[threadIdx.x];
    __syncthreads();

    int tid = blockIdx.x*256+threadIdx.x;
    int p = tid*2;
    if (p >= NPAIR) return;

    // invert p -> (i,j) with i<j ; fp32 sqrt + exact fixup
    int disc = (2*NN-1)*(2*NN-1) - 8*p;     // < 2^24, exact in fp32
    float sq = sqrtf((float)disc);
    int i = (int)(((float)(2*NN-1) - sq)*0.5f);
    if (i<0) i=0; if (i>NN-2) i=NN-2;
    while (i < NN-2 && rowstart(i+1)<=p) i++;
    while (i > 0    && rowstart(i)  > p) i--;
    int j = p - rowstart(i) + i + 1;
    int i2=i, j2=j+1;
    if (j2>=NN){ i2=i+1; j2=i2+1; }

    const float4* Ai  = (const float4*)(g_A + i *32);
    const float4* Ai2 = (const float4*)(g_A + i2*32);
    const float4* Bj  = (const float4*)(g_B + j *32);
    const float4* Bj2 = (const float4*)(g_B + j2*32);

    float h1a[32], h1b[32];
#pragma unroll
    for(int f=0;f<8;f++){
        float4 a  = Ai[f],  bb = Bj[f];
        float4 a2 = Ai2[f], b2v= Bj2[f];
        h1a[f*4+0]=leaky(a.x+bb.x);  h1a[f*4+1]=leaky(a.y+bb.y);
        h1a[f*4+2]=leaky(a.z+bb.z);  h1a[f*4+3]=leaky(a.w+bb.w);
        h1b[f*4+0]=leaky(a2.x+b2v.x); h1b[f*4+1]=leaky(a2.y+b2v.y);
        h1b[f*4+2]=leaky(a2.z+b2v.z); h1b[f*4+3]=leaky(a2.w+b2v.w);
    }

    float y0a=sb3[0], y1a=sb3[1], y0b=sb3[0], y1b=sb3[1];
#pragma unroll 4
    for(int o=0;o<32;o++){
        float aa=sb2[o], ab=sb2[o];
#pragma unroll
        for(int f=0;f<32;f++){
            float ww=sW2[o*32+f];
            aa+=ww*h1a[f]; ab+=ww*h1b[f];
        }
        float h2a=leaky(aa), h2b=leaky(ab);
        float w30=sW3[o], w31=sW3[32+o];
        y0a+=h2a*w30; y1a+=h2a*w31;
        y0b+=h2b*w30; y1b+=h2b*w31;
    }
    *((float4*)(out + (size_t)p*2)) = make_float4(y0a,y1a,y0b,y1b);
}

// ---------------- launch: exactly 6 kernels (k_pairs is launch #6) ----------
extern "C" void kernel_launch(void* const* d_in, const int* in_sizes, int n_in,
                              void* d_out, int out_size){
    const float* feat   = (const float*)d_in[0];
    const float* bn_g   = (const float*)d_in[1];
    const float* bn_b   = (const float*)d_in[2];
    const float* ec1_w1 = (const float*)d_in[3];
    const float* ec1_b1 = (const float*)d_in[4];
    const float* ec1_w2 = (const float*)d_in[5];
    const float* ec1_b2 = (const float*)d_in[6];
    const float* ec2_w1 = (const float*)d_in[7];
    const float* ec2_b1 = (const float*)d_in[8];
    const float* ec2_w2 = (const float*)d_in[9];
    const float* ec2_b2 = (const float*)d_in[10];
    const float* lbn_g  = (const float*)d_in[11];
    const float* lbn_b  = (const float*)d_in[12];
    const float* l_w1   = (const float*)d_in[13];
    const float* l_b1   = (const float*)d_in[14];
    const float* l_w2   = (const float*)d_in[15];
    const float* l_b2   = (const float*)d_in[16];
    const float* l_w3   = (const float*)d_in[17];
    const float* l_b3   = (const float*)d_in[18];
    float* out = (float*)d_out;

    k_statsT<<<72, 256>>>(feat, ec1_w1, ec2_w1);
    k_norm  <<<144, 256>>>(feat, bn_g, bn_b, out + (size_t)2*NPAIR);
    k_knn   <<<NN/8, 256>>>();
    k_edge1 <<<NN/8, 256>>>(ec1_b1, ec1_w2, ec1_b2);
    k_tail  <<<TAILBLK, 256>>>(ec2_b1, ec2_w2, ec2_b2, l_w1, l_b1, lbn_g, lbn_b);
    k_pairs <<<(NPAIR/2+255)/256, 256>>>(l_w2, l_b2, l_w3, l_b3, out);
}

// round 3
// speedup vs baseline: 1.0748x; 1.0748x over previous
#include <cuda_runtime.h>
#include <math.h>

#define NN      1024
#define KNN     8
#define D_IN    36
#define NPAIR   (NN*(NN-1)/2)    // 523776
#define EPSV    1e-5f
#define SLOPE   0.01f

// ---------------- device scratch (no allocations allowed) ----------------
__device__ float g_node[NN*100];          // [x(36) | e1(32) | e2(32)] per node
__device__ float g_mean[D_IN], g_scale[D_IN];
__device__ float4 g_xy[NN];               // compact first-4 normalized feats
__device__ int   g_idx[NN*KNN];
__device__ float4 g_w1t1[72*32];          // ec1_w1 packed: [tt][o] = row o, cols 4tt..4tt+3
__device__ float4 g_w1t2[64*32];          // ec2_w1 packed likewise
__device__ float g_m1[100], g_s1[100], g_m2[100], g_s2[100];
__device__ float g_W1p[200*32];           // BN-scaled l_w1, layout [f][o]
__device__ float g_c[32];                 // folded bias for first pair layer
__device__ float g_A[NN*32];
__device__ float g_B[NN*32];
__device__ unsigned int g_bar;            // grid-sync ticket counter (monotonic)

__device__ __forceinline__ float leaky(float x){ return fmaxf(x, SLOPE*x); }
__device__ __forceinline__ int rowstart(int i){ return i*NN - ((i*(i+1))>>1); }

// software grid barrier: all blocks must be co-resident (grid<=148, 1 CTA/SM)
__device__ __forceinline__ void gridsync(unsigned int nblk){
    __threadfence();                 // release
    __syncthreads();
    if (threadIdx.x == 0){
        unsigned int t = atomicAdd(&g_bar, 1u);
        unsigned int target = t - (t % nblk) + nblk;
        volatile unsigned int* vb = &g_bar;
        while (*vb < target) {}
        __threadfence();             // acquire
    }
    __syncthreads();
}

// ---------------- 1) BN stats (blocks 0..35) + weight pack (36..71) ----
__global__ void k_statsT(const float* __restrict__ feat,
                         const float* __restrict__ w1, const float* __restrict__ w2){
    if (blockIdx.x < 36){
        int f = blockIdx.x;
        __shared__ float ss[256], sq[256];
        float s=0.f, q=0.f;
        for(int i=threadIdx.x;i<NN;i+=256){ float v=feat[i*D_IN+f]; s+=v; q+=v*v; }
        ss[threadIdx.x]=s; sq[threadIdx.x]=q; __syncthreads();
        for(int o=128;o>0;o>>=1){
            if(threadIdx.x<o){ ss[threadIdx.x]+=ss[threadIdx.x+o]; sq[threadIdx.x]+=sq[threadIdx.x+o]; }
            __syncthreads();
        }
        if(threadIdx.x==0){
            float m=ss[0]*(1.f/NN);
            float var=sq[0]*(1.f/NN)-m*m;
            g_mean[f]=m; g_scale[f]=rsqrtf(var+EPSV);
        }
    } else {
        int t = (blockIdx.x-36)*256 + threadIdx.x;
        if (t < 72*32){          // ec1: 2304 float4
            int tt=t>>5, o=t&31;
            g_w1t1[t] = *(const float4*)(w1 + o*288 + 4*tt);
        }
        if (t < 64*32){          // ec2: 2048 float4
            int tt=t>>5, o=t&31;
            g_w1t2[t] = *(const float4*)(w2 + o*256 + 4*tt);
        }
    }
}

// ---------------- 2) normalize x into g_node; emit cells + compact coords ----
__global__ void k_norm(const float* __restrict__ feat, const float* __restrict__ bng,
                       const float* __restrict__ bnb, float* __restrict__ out_cells){
    int t = blockIdx.x*blockDim.x + threadIdx.x;
    if (t < NN*D_IN){
        int i=t/D_IN, f=t%D_IN;
        float v = (feat[t]-g_mean[f])*g_scale[f]*bng[f]+bnb[f];
        g_node[i*100+f] = v;
        if (f < 4) ((float*)g_xy)[i*4+f] = v;
    }
    if (t < NN*5){
        int i=t/5, c=t%5;
        out_cells[i*5+c] = feat[i*D_IN+c];
    }
}

// ---------------- 3) kNN via shared coords + early-reject insertion ----------
__global__ void __launch_bounds__(256) k_knn(){
    __shared__ float4 sxy[NN];       // 16 KB
    for(int t=threadIdx.x; t<NN; t+=256) sxy[t] = g_xy[t];
    __syncthreads();

    int w = threadIdx.x>>5, lane = threadIdx.x&31;
    int node = blockIdx.x*8 + w;
    const float4 xi = sxy[node];

    float d8[8]; int id8[8];
#pragma unroll
    for(int k=0;k<8;k++){ d8[k]=3.4e38f; id8[k]=0x7fffffff; }
    float kth = 3.4e38f; int kthi = 0x7fffffff;

    for(int it=0; it<NN/32; it++){
        int j = lane + it*32;
        float4 xj = sxy[j];
        float cd = fabsf(xi.x-xj.x)+fabsf(xi.y-xj.y)+fabsf(xi.z-xj.z)+fabsf(xi.w-xj.w);
        int ci = j;
        if (cd < kth || (cd==kth && ci < kthi)){
#pragma unroll
            for(int k=0;k<8;k++){
                bool sw = (cd < d8[k]) || (cd==d8[k] && ci < id8[k]);
                float td = sw ? d8[k] : cd; int ti = sw ? id8[k] : ci;
                d8[k]  = sw ? cd : d8[k]; id8[k] = sw ? ci : id8[k];
                cd=td; ci=ti;
            }
            kth = d8[7]; kthi = id8[7];
        }
    }
    for(int r=0;r<8;r++){
        float bd=d8[0]; int bi=id8[0];
#pragma unroll
        for(int off=16;off>0;off>>=1){
            float od=__shfl_xor_sync(0xffffffffu,bd,off);
            int   oi=__shfl_xor_sync(0xffffffffu,bi,off);
            if (od<bd || (od==bd && oi<bi)){ bd=od; bi=oi; }
        }
        if (lane==0) g_idx[node*KNN+r]=bi;
        if (id8[0]==bi){
#pragma unroll
            for(int k=0;k<7;k++){ d8[k]=d8[k+1]; id8[k]=id8[k+1]; }
            d8[7]=3.4e38f; id8[7]=0x7fffffff;
        }
    }
}

// ---------------- 4) edge conv 1 (SMEM weights, float4, 4 acc chains) --------
__global__ void __launch_bounds__(256) k_edge1(const float* __restrict__ b1,
                        const float* __restrict__ w2, const float* __restrict__ b2){
    __shared__ float4 sw4[72*32];    // 36 KB
    __shared__ float4 sv4[8][72];    // 9 KB
    __shared__ float  sh[8][32];
    int w = threadIdx.x>>5, lane = threadIdx.x&31;
    int node = blockIdx.x*8 + w;

    for(int t=threadIdx.x;t<72*32;t+=256) sw4[t]=g_w1t1[t];

    float* svf = (float*)sv4[w];
    for(int t=lane;t<288;t+=32){
        int f=t>>3, k=t&7;
        svf[t] = g_node[g_idx[node*KNN+k]*100 + f];
    }
    __syncthreads();

    float a0=0.f,a1=0.f,a2=0.f,a3=0.f;
#pragma unroll
    for(int tt=0;tt<72;tt++){
        float4 wv = sw4[tt*32+lane];
        float4 vv = sv4[w][tt];
        a0+=wv.x*vv.x; a1+=wv.y*vv.y; a2+=wv.z*vv.z; a3+=wv.w*vv.w;
    }
    sh[w][lane]=leaky(b1[lane]+((a0+a1)+(a2+a3)));
    __syncwarp();

    float acc2 = b2[lane];
    const float4* w2v = (const float4*)(w2 + lane*32);
#pragma unroll
    for(int q=0;q<8;q++){
        float4 wv=w2v[q];
        acc2 += wv.x*sh[w][4*q]+wv.y*sh[w][4*q+1]+wv.z*sh[w][4*q+2]+wv.w*sh[w][4*q+3];
    }
    g_node[node*100+36+lane]=leaky(acc2);
}

// ---------------- 5) fused tail: edge2 -> pstats -> w1p -> ab (grid-synced) ----
#define TAILBLK 128
__global__ void __launch_bounds__(256) k_tail(
        const float* __restrict__ b1, const float* __restrict__ w2,
        const float* __restrict__ b2,
        const float* __restrict__ lw1, const float* __restrict__ lb1,
        const float* __restrict__ lbng, const float* __restrict__ lbnb){
    __shared__ float4 sw4[64*32];    // 32 KB (phase A); reused by B/D as float
    __shared__ float4 sv4[8][64];    // 8 KB
    __shared__ float  sh[8][32];
    int w = threadIdx.x>>5, lane = threadIdx.x&31;

    // ---- phase A: edge conv 2 ----
    {
        int node = blockIdx.x*8 + w;
        for(int t=threadIdx.x;t<64*32;t+=256) sw4[t]=g_w1t2[t];
        float* svf = (float*)sv4[w];
        for(int t=lane;t<256;t+=32){
            int f=t>>3, k=t&7;
            svf[t] = g_node[g_idx[node*KNN+k]*100 + 36 + f];
        }
        __syncthreads();
        float a0=0.f,a1=0.f,a2=0.f,a3=0.f;
#pragma unroll
        for(int tt=0;tt<64;tt++){
            float4 wv = sw4[tt*32+lane];
            float4 vv = sv4[w][tt];
            a0+=wv.x*vv.x; a1+=wv.y*vv.y; a2+=wv.z*vv.z; a3+=wv.w*vv.w;
        }
        sh[w][lane]=leaky(b1[lane]+((a0+a1)+(a2+a3)));
        __syncwarp();
        float acc2 = b2[lane];
        const float4* w2v = (const float4*)(w2 + lane*32);
#pragma unroll
        for(int q=0;q<8;q++){
            float4 wv=w2v[q];
            acc2 += wv.x*sh[w][4*q]+wv.y*sh[w][4*q+1]+wv.z*sh[w][4*q+2]+wv.w*sh[w][4*q+3];
        }
        g_node[node*100+68+lane]=leaky(acc2);
    }
    gridsync(TAILBLK);

    // ---- phase B: pair-BN stats via weighted node moments (blocks 0..99) ----
    if (blockIdx.x < 100){
        int f = blockIdx.x;
        float (*s)[256] = (float(*)[256])sw4;
        float sa=0,qa=0,sb=0,qb=0;
        for(int i=threadIdx.x;i<NN;i+=256){
            float v=__ldcg(&g_node[i*100+f]);
            float wa=(float)(NN-1-i), wb=(float)i;
            sa+=wa*v; qa+=wa*v*v; sb+=wb*v; qb+=wb*v*v;
        }
        s[0][threadIdx.x]=sa; s[1][threadIdx.x]=qa; s[2][threadIdx.x]=sb; s[3][threadIdx.x]=qb;
        __syncthreads();
        for(int o=128;o>0;o>>=1){
            if(threadIdx.x<o){
#pragma unroll
                for(int c=0;c<4;c++) s[c][threadIdx.x]+=s[c][threadIdx.x+o];
            }
            __syncthreads();
        }
        if(threadIdx.x==0){
            const float invP = 1.0f/(float)NPAIR;
            float m1=s[0][0]*invP, q1=s[1][0]*invP;
            float m2=s[2][0]*invP, q2=s[3][0]*invP;
            g_m1[f]=m1; g_s1[f]=rsqrtf(q1-m1*m1+EPSV);
            g_m2[f]=m2; g_s2[f]=rsqrtf(q2-m2*m2+EPSV);
        }
    } else {
        __syncthreads();
    }
    gridsync(TAILBLK);

    // ---- phase C: fold BN into W1 (distributed) + folded bias (block 0) ----
    for(int t=blockIdx.x*256+threadIdx.x; t<6400; t+=TAILBLK*256){
        int o=t&31, f=t>>5;
        float sc = (f<100)? lbng[f]*__ldcg(&g_s1[f]) : lbng[f]*__ldcg(&g_s2[f-100]);
        g_W1p[t] = lw1[o*200+f]*sc;
    }
    if (blockIdx.x==0 && threadIdx.x<32){
        int o=threadIdx.x;
        float c=lb1[o];
        for(int f=0;f<200;f++){
            float m  = (f<100)? __ldcg(&g_m1[f]) : __ldcg(&g_m2[f-100]);
            float sc = (f<100)? lbng[f]*__ldcg(&g_s1[f]) : lbng[f]*__ldcg(&g_s2[f-100]);
            c += lw1[o*200+f]*(lbnb[f]-m*sc);
        }
        g_c[o]=c;
    }
    gridsync(TAILBLK);

    // ---- phase D: per-node projections A (with c folded) and B ----
    {
        float (*srow)[100] = (float(*)[100])sw4;
        int node = blockIdx.x*8+w;
        for(int f=lane;f<100;f+=32) srow[w][f]=__ldcg(&g_node[node*100+f]);
        __syncwarp();
        float a=__ldcg(&g_c[lane]), b=0.f;
        for(int f=0;f<100;f++){
            float v=srow[w][f];
            a += v*__ldcg(&g_W1p[f*32+lane]);
            b += v*__ldcg(&g_W1p[(100+f)*32+lane]);
        }
        g_A[node*32+lane]=a;
        g_B[node*32+lane]=b;
    }
}

// ---------------- 6) the big pair kernel: 2 pairs/thread, float4 weights ------
__global__ void __launch_bounds__(256) k_pairs(const float* __restrict__ lw2,
                                               const float* __restrict__ lb2,
                                               const float* __restrict__ lw3,
                                               const float* __restrict__ lb3,
                                               float* __restrict__ out){
    __shared__ float4 sW2v[256];     // 32 rows x 8 float4
    __shared__ float sb2[32], sW3[64], sb3[2];
    for(int t=threadIdx.x;t<256;t+=256) sW2v[t]=((const float4*)lw2)[t];
    if(threadIdx.x<32) sb2[threadIdx.x]=lb2[threadIdx.x];
    if(threadIdx.x<64) sW3[threadIdx.x]=lw3[threadIdx.x];
    if(threadIdx.x<2)  sb3[threadIdx.x]=lb3[threadIdx.x];
    __syncthreads();

    int tid = blockIdx.x*256+threadIdx.x;
    int p = tid*2;
    if (p >= NPAIR) return;

    // invert p -> (i,j) with i<j ; fp32 sqrt + exact fixup
    int disc = (2*NN-1)*(2*NN-1) - 8*p;     // < 2^24, exact in fp32
    float sq = sqrtf((float)disc);
    int i = (int)(((float)(2*NN-1) - sq)*0.5f);
    if (i<0) i=0; if (i>NN-2) i=NN-2;
    while (i < NN-2 && rowstart(i+1)<=p) i++;
    while (i > 0    && rowstart(i)  > p) i--;
    int j = p - rowstart(i) + i + 1;
    int i2=i, j2=j+1;
    if (j2>=NN){ i2=i+1; j2=i2+1; }

    const float4* Ai  = (const float4*)(g_A + i *32);
    const float4* Ai2 = (const float4*)(g_A + i2*32);
    const float4* Bj  = (const float4*)(g_B + j *32);
    const float4* Bj2 = (const float4*)(g_B + j2*32);

    float h1a[32], h1b[32];
#pragma unroll
    for(int f=0;f<8;f++){
        float4 a  = Ai[f],  bb = Bj[f];
        float4 a2 = Ai2[f], b2v= Bj2[f];
        h1a[f*4+0]=leaky(a.x+bb.x);  h1a[f*4+1]=leaky(a.y+bb.y);
        h1a[f*4+2]=leaky(a.z+bb.z);  h1a[f*4+3]=leaky(a.w+bb.w);
        h1b[f*4+0]=leaky(a2.x+b2v.x); h1b[f*4+1]=leaky(a2.y+b2v.y);
        h1b[f*4+2]=leaky(a2.z+b2v.z); h1b[f*4+3]=leaky(a2.w+b2v.w);
    }

    float y0a=sb3[0], y1a=sb3[1], y0b=sb3[0], y1b=sb3[1];
#pragma unroll 4
    for(int o=0;o<32;o++){
        float aa=sb2[o], ab=sb2[o];
#pragma unroll
        for(int q=0;q<8;q++){
            float4 wv = sW2v[o*8+q];
            aa += wv.x*h1a[4*q]+wv.y*h1a[4*q+1]+wv.z*h1a[4*q+2]+wv.w*h1a[4*q+3];
            ab += wv.x*h1b[4*q]+wv.y*h1b[4*q+1]+wv.z*h1b[4*q+2]+wv.w*h1b[4*q+3];
        }
        float h2a=leaky(aa), h2b=leaky(ab);
        float w30=sW3[o], w31=sW3[32+o];
        y0a+=h2a*w30; y1a+=h2a*w31;
        y0b+=h2b*w30; y1b+=h2b*w31;
    }
    *((float4*)(out + (size_t)p*2)) = make_float4(y0a,y1a,y0b,y1b);
}

// ---------------- launch: exactly 6 kernels ----------
extern "C" void kernel_launch(void* const* d_in, const int* in_sizes, int n_in,
                              void* d_out, int out_size){
    const float* feat   = (const float*)d_in[0];
    const float* bn_g   = (const float*)d_in[1];
    const float* bn_b   = (const float*)d_in[2];
    const float* ec1_w1 = (const float*)d_in[3];
    const float* ec1_b1 = (const float*)d_in[4];
    const float* ec1_w2 = (const float*)d_in[5];
    const float* ec1_b2 = (const float*)d_in[6];
    const float* ec2_w1 = (const float*)d_in[7];
    const float* ec2_b1 = (const float*)d_in[8];
    const float* ec2_w2 = (const float*)d_in[9];
    const float* ec2_b2 = (const float*)d_in[10];
    const float* lbn_g  = (const float*)d_in[11];
    const float* lbn_b  = (const float*)d_in[12];
    const float* l_w1   = (const float*)d_in[13];
    const float* l_b1   = (const float*)d_in[14];
    const float* l_w2   = (const float*)d_in[15];
    const float* l_b2   = (const float*)d_in[16];
    const float* l_w3   = (const float*)d_in[17];
    const float* l_b3   = (const float*)d_in[18];
    float* out = (float*)d_out;

    k_statsT<<<72, 256>>>(feat, ec1_w1, ec2_w1);
    k_norm  <<<144, 256>>>(feat, bn_g, bn_b, out + (size_t)2*NPAIR);
    k_knn   <<<NN/8, 256>>>();
    k_edge1 <<<NN/8, 256>>>(ec1_b1, ec1_w2, ec1_b2);
    k_tail  <<<TAILBLK, 256>>>(ec2_b1, ec2_w2, ec2_b2, l_w1, l_b1, lbn_g, lbn_b);
    k_pairs <<<(NPAIR/2+255)/256, 256>>>(l_w2, l_b2, l_w3, l_b3, out);
}

// round 4
// speedup vs baseline: 1.1073x; 1.0302x over previous
#include <cuda_runtime.h>
#include <math.h>

#define NN      1024
#define KNN     8
#define D_IN    36
#define NPAIR   (NN*(NN-1)/2)    // 523776
#define EPSV    1e-5f
#define SLOPE   0.01f
#define PREPBLK 128

// ---------------- device scratch ----------------
__device__ float g_node[NN*100];          // [x(36) | e1(32) | e2(32)] per node
__device__ float g_mean[D_IN], g_scale[D_IN];
__device__ float4 g_xy[NN];
__device__ int   g_idx[NN*KNN];
__device__ float4 g_w1t1[72*32];          // ec1_w1 packed: [tt][o]
__device__ float4 g_w1t2[64*32];
__device__ float g_m1[100], g_s1[100], g_m2[100], g_s2[100];
__device__ float g_W1p[200*32];           // BN-scaled l_w1, layout [f][o]
__device__ float g_c[32];
__device__ float g_A[NN*32];
__device__ float g_B[NN*32];
__device__ unsigned int g_bar;

__device__ __forceinline__ float leaky(float x){ return fmaxf(x, SLOPE*x); }
__device__ __forceinline__ int rowstart(int i){ return i*NN - ((i*(i+1))>>1); }

__device__ __forceinline__ void gridsync(unsigned int nblk){
    __threadfence();
    __syncthreads();
    if (threadIdx.x == 0){
        unsigned int t = atomicAdd(&g_bar, 1u);
        unsigned int target = t - (t % nblk) + nblk;
        volatile unsigned int* vb = &g_bar;
        while (*vb < target) {}
        __threadfence();
    }
    __syncthreads();
}

// f32x2 packed helpers (Blackwell)
__device__ __forceinline__ unsigned long long pk2(float lo, float hi){
    unsigned long long r; asm("mov.b64 %0,{%1,%2};":"=l"(r):"f"(lo),"f"(hi)); return r;
}
__device__ __forceinline__ void upk2(unsigned long long v, float& lo, float& hi){
    asm("mov.b64 {%0,%1},%2;":"=f"(lo),"=f"(hi):"l"(v));
}
__device__ __forceinline__ unsigned long long fma2(unsigned long long a,
                       unsigned long long b, unsigned long long c){
    unsigned long long d;
    asm("fma.rn.f32x2 %0,%1,%2,%3;":"=l"(d):"l"(a),"l"(b),"l"(c));
    return d;
}

// =====================================================================
// Persistent prep kernel: 8 phases, 128 blocks x 512 threads
// =====================================================================
__global__ void __launch_bounds__(512) k_prep(
        const float* __restrict__ feat,
        const float* __restrict__ bng,  const float* __restrict__ bnb,
        const float* __restrict__ e1w1, const float* __restrict__ e1b1,
        const float* __restrict__ e1w2, const float* __restrict__ e1b2,
        const float* __restrict__ e2w1, const float* __restrict__ e2b1,
        const float* __restrict__ e2w2, const float* __restrict__ e2b2,
        const float* __restrict__ lw1,  const float* __restrict__ lb1,
        const float* __restrict__ lbng, const float* __restrict__ lbnb,
        float* __restrict__ out_cells){
    extern __shared__ char sm_[];
    const int tid = threadIdx.x;
    const int bid = blockIdx.x;
    const int w   = tid>>5, lane = tid&31;

    // ---------- P0: BN stats (blocks 0..35) | weight pack (36..71) ----------
    if (bid < 36){
        int f = bid;
        float* ss = (float*)sm_;          // [512]
        float* sq = ss+512;
        float s=0.f, q=0.f;
        for(int i=tid;i<NN;i+=512){ float v=feat[i*D_IN+f]; s+=v; q+=v*v; }
        ss[tid]=s; sq[tid]=q; __syncthreads();
        for(int o=256;o>0;o>>=1){
            if(tid<o){ ss[tid]+=ss[tid+o]; sq[tid]+=sq[tid+o]; }
            __syncthreads();
        }
        if(tid==0){
            float m=ss[0]*(1.f/NN);
            float var=sq[0]*(1.f/NN)-m*m;
            g_mean[f]=m; g_scale[f]=rsqrtf(var+EPSV);
        }
    } else if (bid < 72){
        int t = (bid-36)*512 + tid;
        if (t < 72*32){ int tt=t>>5, o=t&31; g_w1t1[t] = *(const float4*)(e1w1 + o*288 + 4*tt); }
        if (t < 64*32){ int tt=t>>5, o=t&31; g_w1t2[t] = *(const float4*)(e2w1 + o*256 + 4*tt); }
    }
    gridsync(PREPBLK);

    // ---------- P1: normalize + cells + compact coords ----------
    {
        int t = bid*512 + tid;
        if (t < NN*D_IN){
            int i=t/D_IN, f=t%D_IN;
            float v = (feat[t]-__ldcg(&g_mean[f]))*__ldcg(&g_scale[f])*bng[f]+bnb[f];
            g_node[i*100+f] = v;
            if (f < 4) ((float*)g_xy)[i*4+f] = v;
        }
        if (t < NN*5){
            int i=t/5, c=t%5;
            out_cells[i*5+c] = feat[i*D_IN+c];
        }
    }
    gridsync(PREPBLK);

    // ---------- P2: kNN, 2 warps per node ----------
    {
        float4* sxy = (float4*)sm_;                       // 16 KB
        float  (*skd)[2][8] = (float(*)[2][8])(sm_+16384);
        int    (*ski)[2][8] = (int  (*)[2][8])(sm_+16384+512);
        for(int t=tid;t<NN;t+=512) sxy[t] = __ldcg(&g_xy[t]);
        __syncthreads();

        int n8 = w>>1, h = w&1;
        int node = bid*8 + n8;
        const float4 xi = sxy[node];

        float d8[8]; int id8[8];
#pragma unroll
        for(int k=0;k<8;k++){ d8[k]=3.4e38f; id8[k]=0x7fffffff; }
        float kth = 3.4e38f; int kthi = 0x7fffffff;
        for(int it=0; it<16; it++){
            int j = 512*h + it*32 + lane;
            float4 xj = sxy[j];
            float cd = fabsf(xi.x-xj.x)+fabsf(xi.y-xj.y)+fabsf(xi.z-xj.z)+fabsf(xi.w-xj.w);
            int ci = j;
            if (cd < kth || (cd==kth && ci < kthi)){
#pragma unroll
                for(int k=0;k<8;k++){
                    bool sw = (cd < d8[k]) || (cd==d8[k] && ci < id8[k]);
                    float td = sw ? d8[k] : cd; int ti = sw ? id8[k] : ci;
                    d8[k]  = sw ? cd : d8[k]; id8[k] = sw ? ci : id8[k];
                    cd=td; ci=ti;
                }
                kth = d8[7]; kthi = id8[7];
            }
        }
        // warp-local: produce sorted top-8 into smem
        for(int r=0;r<8;r++){
            float bd=d8[0]; int bi=id8[0];
#pragma unroll
            for(int off=16;off>0;off>>=1){
                float od=__shfl_xor_sync(0xffffffffu,bd,off);
                int   oi=__shfl_xor_sync(0xffffffffu,bi,off);
                if (od<bd || (od==bd && oi<bi)){ bd=od; bi=oi; }
            }
            if (lane==0){ skd[n8][h][r]=bd; ski[n8][h][r]=bi; }
            if (id8[0]==bi){
#pragma unroll
                for(int k=0;k<7;k++){ d8[k]=d8[k+1]; id8[k]=id8[k+1]; }
                d8[7]=3.4e38f; id8[7]=0x7fffffff;
            }
        }
        __syncthreads();
        // merge two sorted 8-lists (warp h==0 per node)
        if (h==0){
            float md = 3.4e38f; int mi = 0x7fffffff;
            if (lane < 16){ md = skd[n8][lane>>3][lane&7]; mi = ski[n8][lane>>3][lane&7]; }
            for(int r=0;r<8;r++){
                float bd=md; int bi=mi;
#pragma unroll
                for(int off=16;off>0;off>>=1){
                    float od=__shfl_xor_sync(0xffffffffu,bd,off);
                    int   oi=__shfl_xor_sync(0xffffffffu,bi,off);
                    if (od<bd || (od==bd && oi<bi)){ bd=od; bi=oi; }
                }
                if (lane==0) g_idx[node*KNN+r]=bi;
                if (md==bd && mi==bi){ md=3.4e38f; mi=0x7fffffff; }
            }
        }
    }
    gridsync(PREPBLK);

    // ---------- P3: edge conv 1, 2 warps per node ----------
    {
        float4* sW  = (float4*)sm_;                         // 36864 B
        float (*sv)[288]   = (float(*)[288])(sm_+36864);    // 9216 B
        float (*sh2)[2][32]= (float(*)[2][32])(sm_+46080);  // 2048 B
        float (*sh1)[32]   = (float(*)[32])(sm_+48128);     // 1024 B
        for(int t=tid;t<72*32;t+=512) sW[t]=__ldcg(&g_w1t1[t]);
        int n8 = w>>1, h = w&1;
        int node = bid*8 + n8;
        for(int t=lane;t<144;t+=32){
            int f = 18*h + (t>>3), k = t&7;
            int nb = __ldcg(&g_idx[node*KNN+k]);
            sv[n8][f*8+k] = __ldcg(&g_node[nb*100+f]);
        }
        __syncthreads();
        float a0=0.f,a1=0.f,a2=0.f,a3=0.f;
        const float4* vv4 = (const float4*)sv[n8];
#pragma unroll
        for(int u=0;u<36;u++){
            int tt = 36*h+u;
            float4 wv = sW[tt*32+lane];
            float4 vv = vv4[tt];
            a0+=wv.x*vv.x; a1+=wv.y*vv.y; a2+=wv.z*vv.z; a3+=wv.w*vv.w;
        }
        sh2[n8][h][lane]=((a0+a1)+(a2+a3));
        __syncthreads();
        if (h==0){
            float acc = sh2[n8][0][lane]+sh2[n8][1][lane]+e1b1[lane];
            sh1[n8][lane]=leaky(acc);
            __syncwarp();
            float acc2 = e1b2[lane];
            const float4* w2v = (const float4*)(e1w2 + lane*32);
#pragma unroll
            for(int q=0;q<8;q++){
                float4 wv=w2v[q];
                acc2 += wv.x*sh1[n8][4*q]+wv.y*sh1[n8][4*q+1]+wv.z*sh1[n8][4*q+2]+wv.w*sh1[n8][4*q+3];
            }
            g_node[node*100+36+lane]=leaky(acc2);
        }
    }
    gridsync(PREPBLK);

    // ---------- P4: edge conv 2, 2 warps per node ----------
    {
        float4* sW  = (float4*)sm_;                         // 32768 B
        float (*sv)[256]   = (float(*)[256])(sm_+32768);    // 8192 B
        float (*sh2)[2][32]= (float(*)[2][32])(sm_+40960);
        float (*sh1)[32]   = (float(*)[32])(sm_+43008);
        for(int t=tid;t<64*32;t+=512) sW[t]=__ldcg(&g_w1t2[t]);
        int n8 = w>>1, h = w&1;
        int node = bid*8 + n8;
        for(int t=lane;t<128;t+=32){
            int f = 16*h + (t>>3), k = t&7;
            int nb = __ldcg(&g_idx[node*KNN+k]);
            sv[n8][f*8+k] = __ldcg(&g_node[nb*100+36+f]);
        }
        __syncthreads();
        float a0=0.f,a1=0.f,a2=0.f,a3=0.f;
        const float4* vv4 = (const float4*)sv[n8];
#pragma unroll
        for(int u=0;u<32;u++){
            int tt = 32*h+u;
            float4 wv = sW[tt*32+lane];
            float4 vv = vv4[tt];
            a0+=wv.x*vv.x; a1+=wv.y*vv.y; a2+=wv.z*vv.z; a3+=wv.w*vv.w;
        }
        sh2[n8][h][lane]=((a0+a1)+(a2+a3));
        __syncthreads();
        if (h==0){
            float acc = sh2[n8][0][lane]+sh2[n8][1][lane]+e2b1[lane];
            sh1[n8][lane]=leaky(acc);
            __syncwarp();
            float acc2 = e2b2[lane];
            const float4* w2v = (const float4*)(e2w2 + lane*32);
#pragma unroll
            for(int q=0;q<8;q++){
                float4 wv=w2v[q];
                acc2 += wv.x*sh1[n8][4*q]+wv.y*sh1[n8][4*q+1]+wv.z*sh1[n8][4*q+2]+wv.w*sh1[n8][4*q+3];
            }
            g_node[node*100+68+lane]=leaky(acc2);
        }
    }
    gridsync(PREPBLK);

    // ---------- P5: pair-BN stats via weighted node moments ----------
    {
        int f = (bid < 100) ? bid : 0;
        float (*s)[512] = (float(*)[512])sm_;   // 4 x 512
        float sa=0,qa=0,sb=0,qb=0;
        for(int i=tid;i<NN;i+=512){
            float v=__ldcg(&g_node[i*100+f]);
            float wa=(float)(NN-1-i), wb=(float)i;
            sa+=wa*v; qa+=wa*v*v; sb+=wb*v; qb+=wb*v*v;
        }
        s[0][tid]=sa; s[1][tid]=qa; s[2][tid]=sb; s[3][tid]=qb;
        __syncthreads();
        for(int o=256;o>0;o>>=1){
            if(tid<o){
#pragma unroll
                for(int c=0;c<4;c++) s[c][tid]+=s[c][tid+o];
            }
            __syncthreads();
        }
        if(tid==0 && bid<100){
            const float invP = 1.0f/(float)NPAIR;
            float m1=s[0][0]*invP, q1=s[1][0]*invP;
            float m2=s[2][0]*invP, q2=s[3][0]*invP;
            g_m1[f]=m1; g_s1[f]=rsqrtf(q1-m1*m1+EPSV);
            g_m2[f]=m2; g_s2[f]=rsqrtf(q2-m2*m2+EPSV);
        }
    }
    gridsync(PREPBLK);

    // ---------- P6: fold BN into W1 + folded bias ----------
    {
        int t = bid*512+tid;
        if (t < 6400){
            int o=t&31, f=t>>5;
            float sc = (f<100)? lbng[f]*__ldcg(&g_s1[f]) : lbng[f]*__ldcg(&g_s2[f-100]);
            g_W1p[t] = lw1[o*200+f]*sc;
        }
        if (bid==0 && tid<32){
            int o=tid;
            float c=lb1[o];
            for(int f=0;f<200;f++){
                float m  = (f<100)? __ldcg(&g_m1[f]) : __ldcg(&g_m2[f-100]);
                float sc = (f<100)? lbng[f]*__ldcg(&g_s1[f]) : lbng[f]*__ldcg(&g_s2[f-100]);
                c += lw1[o*200+f]*(lbnb[f]-m*sc);
            }
            g_c[o]=c;
        }
    }
    gridsync(PREPBLK);

    // ---------- P7: per-node projections A,B — 2 warps per node ----------
    {
        float* sWp = (float*)sm_;                              // 25600 B
        float (*sv)[100]    = (float(*)[100])(sm_+25600);      // 3200 B
        float (*spa)[2][32] = (float(*)[2][32])(sm_+28800);    // 2048
        float (*spb)[2][32] = (float(*)[2][32])(sm_+30848);    // 2048
        for(int t=tid;t<6400;t+=512) sWp[t]=__ldcg(&g_W1p[t]);
        int n8 = w>>1, h = w&1;
        int node = bid*8 + n8;
        for(int t=lane;t<50;t+=32){
            int f = 50*h + t;
            sv[n8][f]=__ldcg(&g_node[node*100+f]);
        }
        __syncthreads();
        float a=0.f, b=0.f;
        for(int u=0;u<50;u++){
            int f = 50*h+u;
            float v=sv[n8][f];
            a += v*sWp[f*32+lane];
            b += v*sWp[(100+f)*32+lane];
        }
        spa[n8][h][lane]=a; spb[n8][h][lane]=b;
        __syncthreads();
        if (h==0){
            g_A[node*32+lane]=spa[n8][0][lane]+spa[n8][1][lane]+__ldcg(&g_c[lane]);
            g_B[node*32+lane]=spb[n8][0][lane]+spb[n8][1][lane];
        }
    }
}

// =====================================================================
// Pair kernel: 2 pairs/thread, packed f32x2 FMA
// =====================================================================
__global__ void __launch_bounds__(256) k_pairs(const float* __restrict__ lw2,
                                               const float* __restrict__ lb2,
                                               const float* __restrict__ lw3,
                                               const float* __restrict__ lb3,
                                               float* __restrict__ out){
    __shared__ float4 sW2d[512];                 // [o][q]: {w2q, w2q, w2q+1, w2q+1}
    __shared__ unsigned long long sb2d[32];
    __shared__ unsigned long long sw3d[64];
    __shared__ unsigned long long sb3d[2];
    for(int t=threadIdx.x;t<512;t+=256){
        int o=t>>4, q=t&15;
        float wa=lw2[o*32+2*q], wb=lw2[o*32+2*q+1];
        sW2d[t]=make_float4(wa,wa,wb,wb);
    }
    if(threadIdx.x<32){
        int o=threadIdx.x;
        sb2d[o]=pk2(lb2[o],lb2[o]);
        sw3d[o]=pk2(lw3[o],lw3[o]);
        sw3d[32+o]=pk2(lw3[32+o],lw3[32+o]);
        if(o<2) sb3d[o]=pk2(lb3[o],lb3[o]);
    }
    __syncthreads();

    int tid = blockIdx.x*256+threadIdx.x;
    int p = tid*2;
    if (p >= NPAIR) return;

    int disc = (2*NN-1)*(2*NN-1) - 8*p;
    float sq = sqrtf((float)disc);
    int i = (int)(((float)(2*NN-1) - sq)*0.5f);
    if (i<0) i=0; if (i>NN-2) i=NN-2;
    while (i < NN-2 && rowstart(i+1)<=p) i++;
    while (i > 0    && rowstart(i)  > p) i--;
    int j = p - rowstart(i) + i + 1;
    int i2=i, j2=j+1;
    if (j2>=NN){ i2=i+1; j2=i2+1; }

    const float4* Ai  = (const float4*)(g_A + i *32);
    const float4* Ai2 = (const float4*)(g_A + i2*32);
    const float4* Bj  = (const float4*)(g_B + j *32);
    const float4* Bj2 = (const float4*)(g_B + j2*32);

    unsigned long long h1p[32];
#pragma unroll
    for(int f=0;f<8;f++){
        float4 a  = Ai[f],  bb = Bj[f];
        float4 a2 = Ai2[f], b2v= Bj2[f];
        h1p[f*4+0]=pk2(leaky(a.x+bb.x), leaky(a2.x+b2v.x));
        h1p[f*4+1]=pk2(leaky(a.y+bb.y), leaky(a2.y+b2v.y));
        h1p[f*4+2]=pk2(leaky(a.z+bb.z), leaky(a2.z+b2v.z));
        h1p[f*4+3]=pk2(leaky(a.w+bb.w), leaky(a2.w+b2v.w));
    }

    unsigned long long y0=sb3d[0], y1=sb3d[1];
    const ulonglong2* w2u = (const ulonglong2*)sW2d;
#pragma unroll 4
    for(int o=0;o<32;o++){
        unsigned long long acc = sb2d[o];
#pragma unroll
        for(int q=0;q<16;q++){
            ulonglong2 wv = w2u[o*16+q];
            acc = fma2(wv.x, h1p[2*q],   acc);
            acc = fma2(wv.y, h1p[2*q+1], acc);
        }
        float aa,ab; upk2(acc,aa,ab);
        unsigned long long h2 = pk2(leaky(aa), leaky(ab));
        y0 = fma2(sw3d[o],    h2, y0);
        y1 = fma2(sw3d[32+o], h2, y1);
    }
    float y0a,y0b,y1a,y1b;
    upk2(y0,y0a,y0b); upk2(y1,y1a,y1b);
    *((float4*)(out + (size_t)p*2)) = make_float4(y0a,y1a,y0b,y1b);
}

// ---------------- launch: 2 kernels ----------------
extern "C" void kernel_launch(void* const* d_in, const int* in_sizes, int n_in,
                              void* d_out, int out_size){
    const float* feat   = (const float*)d_in[0];
    const float* bn_g   = (const float*)d_in[1];
    const float* bn_b   = (const float*)d_in[2];
    const float* ec1_w1 = (const float*)d_in[3];
    const float* ec1_b1 = (const float*)d_in[4];
    const float* ec1_w2 = (const float*)d_in[5];
    const float* ec1_b2 = (const float*)d_in[6];
    const float* ec2_w1 = (const float*)d_in[7];
    const float* ec2_b1 = (const float*)d_in[8];
    const float* ec2_w2 = (const float*)d_in[9];
    const float* ec2_b2 = (const float*)d_in[10];
    const float* lbn_g  = (const float*)d_in[11];
    const float* lbn_b  = (const float*)d_in[12];
    const float* l_w1   = (const float*)d_in[13];
    const float* l_b1   = (const float*)d_in[14];
    const float* l_w2   = (const float*)d_in[15];
    const float* l_b2   = (const float*)d_in[16];
    const float* l_w3   = (const float*)d_in[17];
    const float* l_b3   = (const float*)d_in[18];
    float* out = (float*)d_out;

    static int attr_done = 0;
    if (!attr_done){
        cudaFuncSetAttribute(k_prep, cudaFuncAttributeMaxDynamicSharedMemorySize, 50176);
        attr_done = 1;
    }

    k_prep <<<PREPBLK, 512, 49152>>>(feat, bn_g, bn_b,
                                     ec1_w1, ec1_b1, ec1_w2, ec1_b2,
                                     ec2_w1, ec2_b1, ec2_w2, ec2_b2,
                                     l_w1, l_b1, lbn_g, lbn_b,
                                     out + (size_t)2*NPAIR);
    k_pairs<<<(NPAIR/2+255)/256, 256>>>(l_w2, l_b2, l_w3, l_b3, out);
}

// round 5
// speedup vs baseline: 1.1591x; 1.0467x over previous
#include <cuda_runtime.h>
#include <math.h>
#include <stdint.h>

#define NN      1024
#define KNN     8
#define D_IN    36
#define NPAIR   (NN*(NN-1)/2)    // 523776
#define EPSV    1e-5f
#define SLOPE   0.01f
#define PREPBLK 128

// ---------------- device scratch ----------------
__device__ float g_node[NN*100];          // [x(36) | e1(32) | e2(32)] per node
__device__ float g_mean[D_IN], g_scale[D_IN];
__device__ float4 g_xy[NN];
__device__ int   g_idx[NN*KNN];
__device__ float4 g_w1t1[72*32];          // ec1_w1 packed: [tt][o]
__device__ float4 g_w1t2[64*32];
__device__ float g_m1[100], g_s1[100], g_m2[100], g_s2[100];
__device__ float g_W1p[200*32];           // BN-scaled l_w1, layout [f][o]
__device__ float g_c[32];
__device__ float g_A[NN*32];
__device__ float g_B[NN*32];
__device__ unsigned int g_bar;

__device__ __forceinline__ float leaky(float x){ return fmaxf(x, SLOPE*x); }
__device__ __forceinline__ int rowstart(int i){ return i*NN - ((i*(i+1))>>1); }

__device__ __forceinline__ void gridsync(unsigned int nblk){
    __threadfence();
    __syncthreads();
    if (threadIdx.x == 0){
        unsigned int t = atomicAdd(&g_bar, 1u);
        unsigned int target = t - (t % nblk) + nblk;
        volatile unsigned int* vb = &g_bar;
        while (*vb < target) {}
        __threadfence();
    }
    __syncthreads();
}

// tf32 helpers
__device__ __forceinline__ uint32_t to_tf32(float v){
    uint32_t r; asm("cvt.rna.tf32.f32 %0,%1;":"=r"(r):"f"(v)); return r;
}
__device__ __forceinline__ void mma_tf32(float* C, const uint32_t* A, const uint32_t* B){
    asm volatile(
      "mma.sync.aligned.m16n8k8.row.col.f32.tf32.tf32.f32 "
      "{%0,%1,%2,%3},{%4,%5,%6,%7},{%8,%9},{%0,%1,%2,%3};"
      : "+f"(C[0]),"+f"(C[1]),"+f"(C[2]),"+f"(C[3])
      : "r"(A[0]),"r"(A[1]),"r"(A[2]),"r"(A[3]),"r"(B[0]),"r"(B[1]));
}

// =====================================================================
// Persistent prep kernel: 8 phases, 128 blocks x 512 threads (unchanged)
// =====================================================================
__global__ void __launch_bounds__(512) k_prep(
        const float* __restrict__ feat,
        const float* __restrict__ bng,  const float* __restrict__ bnb,
        const float* __restrict__ e1w1, const float* __restrict__ e1b1,
        const float* __restrict__ e1w2, const float* __restrict__ e1b2,
        const float* __restrict__ e2w1, const float* __restrict__ e2b1,
        const float* __restrict__ e2w2, const float* __restrict__ e2b2,
        const float* __restrict__ lw1,  const float* __restrict__ lb1,
        const float* __restrict__ lbng, const float* __restrict__ lbnb,
        float* __restrict__ out_cells){
    extern __shared__ char sm_[];
    const int tid = threadIdx.x;
    const int bid = blockIdx.x;
    const int w   = tid>>5, lane = tid&31;

    // ---------- P0: BN stats (blocks 0..35) | weight pack (36..71) ----------
    if (bid < 36){
        int f = bid;
        float* ss = (float*)sm_;
        float* sq = ss+512;
        float s=0.f, q=0.f;
        for(int i=tid;i<NN;i+=512){ float v=feat[i*D_IN+f]; s+=v; q+=v*v; }
        ss[tid]=s; sq[tid]=q; __syncthreads();
        for(int o=256;o>0;o>>=1){
            if(tid<o){ ss[tid]+=ss[tid+o]; sq[tid]+=sq[tid+o]; }
            __syncthreads();
        }
        if(tid==0){
            float m=ss[0]*(1.f/NN);
            float var=sq[0]*(1.f/NN)-m*m;
            g_mean[f]=m; g_scale[f]=rsqrtf(var+EPSV);
        }
    } else if (bid < 72){
        int t = (bid-36)*512 + tid;
        if (t < 72*32){ int tt=t>>5, o=t&31; g_w1t1[t] = *(const float4*)(e1w1 + o*288 + 4*tt); }
        if (t < 64*32){ int tt=t>>5, o=t&31; g_w1t2[t] = *(const float4*)(e2w1 + o*256 + 4*tt); }
    }
    gridsync(PREPBLK);

    // ---------- P1: normalize + cells + compact coords ----------
    {
        int t = bid*512 + tid;
        if (t < NN*D_IN){
            int i=t/D_IN, f=t%D_IN;
            float v = (feat[t]-__ldcg(&g_mean[f]))*__ldcg(&g_scale[f])*bng[f]+bnb[f];
            g_node[i*100+f] = v;
            if (f < 4) ((float*)g_xy)[i*4+f] = v;
        }
        if (t < NN*5){
            int i=t/5, c=t%5;
            out_cells[i*5+c] = feat[i*D_IN+c];
        }
    }
    gridsync(PREPBLK);

    // ---------- P2: kNN, 2 warps per node ----------
    {
        float4* sxy = (float4*)sm_;
        float  (*skd)[2][8] = (float(*)[2][8])(sm_+16384);
        int    (*ski)[2][8] = (int  (*)[2][8])(sm_+16384+512);
        for(int t=tid;t<NN;t+=512) sxy[t] = __ldcg(&g_xy[t]);
        __syncthreads();

        int n8 = w>>1, h = w&1;
        int node = bid*8 + n8;
        const float4 xi = sxy[node];

        float d8[8]; int id8[8];
#pragma unroll
        for(int k=0;k<8;k++){ d8[k]=3.4e38f; id8[k]=0x7fffffff; }
        float kth = 3.4e38f; int kthi = 0x7fffffff;
        for(int it=0; it<16; it++){
            int j = 512*h + it*32 + lane;
            float4 xj = sxy[j];
            float cd = fabsf(xi.x-xj.x)+fabsf(xi.y-xj.y)+fabsf(xi.z-xj.z)+fabsf(xi.w-xj.w);
            int ci = j;
            if (cd < kth || (cd==kth && ci < kthi)){
#pragma unroll
                for(int k=0;k<8;k++){
                    bool sw = (cd < d8[k]) || (cd==d8[k] && ci < id8[k]);
                    float td = sw ? d8[k] : cd; int ti = sw ? id8[k] : ci;
                    d8[k]  = sw ? cd : d8[k]; id8[k] = sw ? ci : id8[k];
                    cd=td; ci=ti;
                }
                kth = d8[7]; kthi = id8[7];
            }
        }
        for(int r=0;r<8;r++){
            float bd=d8[0]; int bi=id8[0];
#pragma unroll
            for(int off=16;off>0;off>>=1){
                float od=__shfl_xor_sync(0xffffffffu,bd,off);
                int   oi=__shfl_xor_sync(0xffffffffu,bi,off);
                if (od<bd || (od==bd && oi<bi)){ bd=od; bi=oi; }
            }
            if (lane==0){ skd[n8][h][r]=bd; ski[n8][h][r]=bi; }
            if (id8[0]==bi){
#pragma unroll
                for(int k=0;k<7;k++){ d8[k]=d8[k+1]; id8[k]=id8[k+1]; }
                d8[7]=3.4e38f; id8[7]=0x7fffffff;
            }
        }
        __syncthreads();
        if (h==0){
            float md = 3.4e38f; int mi = 0x7fffffff;
            if (lane < 16){ md = skd[n8][lane>>3][lane&7]; mi = ski[n8][lane>>3][lane&7]; }
            for(int r=0;r<8;r++){
                float bd=md; int bi=mi;
#pragma unroll
                for(int off=16;off>0;off>>=1){
                    float od=__shfl_xor_sync(0xffffffffu,bd,off);
                    int   oi=__shfl_xor_sync(0xffffffffu,bi,off);
                    if (od<bd || (od==bd && oi<bi)){ bd=od; bi=oi; }
                }
                if (lane==0) g_idx[node*KNN+r]=bi;
                if (md==bd && mi==bi){ md=3.4e38f; mi=0x7fffffff; }
            }
        }
    }
    gridsync(PREPBLK);

    // ---------- P3: edge conv 1, 2 warps per node ----------
    {
        float4* sW  = (float4*)sm_;
        float (*sv)[288]   = (float(*)[288])(sm_+36864);
        float (*sh2)[2][32]= (float(*)[2][32])(sm_+46080);
        float (*sh1)[32]   = (float(*)[32])(sm_+48128);
        for(int t=tid;t<72*32;t+=512) sW[t]=__ldcg(&g_w1t1[t]);
        int n8 = w>>1, h = w&1;
        int node = bid*8 + n8;
        for(int t=lane;t<144;t+=32){
            int f = 18*h + (t>>3), k = t&7;
            int nb = __ldcg(&g_idx[node*KNN+k]);
            sv[n8][f*8+k] = __ldcg(&g_node[nb*100+f]);
        }
        __syncthreads();
        float a0=0.f,a1=0.f,a2=0.f,a3=0.f;
        const float4* vv4 = (const float4*)sv[n8];
#pragma unroll
        for(int u=0;u<36;u++){
            int tt = 36*h+u;
            float4 wv = sW[tt*32+lane];
            float4 vv = vv4[tt];
            a0+=wv.x*vv.x; a1+=wv.y*vv.y; a2+=wv.z*vv.z; a3+=wv.w*vv.w;
        }
        sh2[n8][h][lane]=((a0+a1)+(a2+a3));
        __syncthreads();
        if (h==0){
            float acc = sh2[n8][0][lane]+sh2[n8][1][lane]+e1b1[lane];
            sh1[n8][lane]=leaky(acc);
            __syncwarp();
            float acc2 = e1b2[lane];
            const float4* w2v = (const float4*)(e1w2 + lane*32);
#pragma unroll
            for(int q=0;q<8;q++){
                float4 wv=w2v[q];
                acc2 += wv.x*sh1[n8][4*q]+wv.y*sh1[n8][4*q+1]+wv.z*sh1[n8][4*q+2]+wv.w*sh1[n8][4*q+3];
            }
            g_node[node*100+36+lane]=leaky(acc2);
        }
    }
    gridsync(PREPBLK);

    // ---------- P4: edge conv 2, 2 warps per node ----------
    {
        float4* sW  = (float4*)sm_;
        float (*sv)[256]   = (float(*)[256])(sm_+32768);
        float (*sh2)[2][32]= (float(*)[2][32])(sm_+40960);
        float (*sh1)[32]   = (float(*)[32])(sm_+43008);
        for(int t=tid;t<64*32;t+=512) sW[t]=__ldcg(&g_w1t2[t]);
        int n8 = w>>1, h = w&1;
        int node = bid*8 + n8;
        for(int t=lane;t<128;t+=32){
            int f = 16*h + (t>>3), k = t&7;
            int nb = __ldcg(&g_idx[node*KNN+k]);
            sv[n8][f*8+k] = __ldcg(&g_node[nb*100+36+f]);
        }
        __syncthreads();
        float a0=0.f,a1=0.f,a2=0.f,a3=0.f;
        const float4* vv4 = (const float4*)sv[n8];
#pragma unroll
        for(int u=0;u<32;u++){
            int tt = 32*h+u;
            float4 wv = sW[tt*32+lane];
            float4 vv = vv4[tt];
            a0+=wv.x*vv.x; a1+=wv.y*vv.y; a2+=wv.z*vv.z; a3+=wv.w*vv.w;
        }
        sh2[n8][h][lane]=((a0+a1)+(a2+a3));
        __syncthreads();
        if (h==0){
            float acc = sh2[n8][0][lane]+sh2[n8][1][lane]+e2b1[lane];
            sh1[n8][lane]=leaky(acc);
            __syncwarp();
            float acc2 = e2b2[lane];
            const float4* w2v = (const float4*)(e2w2 + lane*32);
#pragma unroll
            for(int q=0;q<8;q++){
                float4 wv=w2v[q];
                acc2 += wv.x*sh1[n8][4*q]+wv.y*sh1[n8][4*q+1]+wv.z*sh1[n8][4*q+2]+wv.w*sh1[n8][4*q+3];
            }
            g_node[node*100+68+lane]=leaky(acc2);
        }
    }
    gridsync(PREPBLK);

    // ---------- P5: pair-BN stats via weighted node moments ----------
    {
        int f = (bid < 100) ? bid : 0;
        float (*s)[512] = (float(*)[512])sm_;
        float sa=0,qa=0,sb=0,qb=0;
        for(int i=tid;i<NN;i+=512){
            float v=__ldcg(&g_node[i*100+f]);
            float wa=(float)(NN-1-i), wb=(float)i;
            sa+=wa*v; qa+=wa*v*v; sb+=wb*v; qb+=wb*v*v;
        }
        s[0][tid]=sa; s[1][tid]=qa; s[2][tid]=sb; s[3][tid]=qb;
        __syncthreads();
        for(int o=256;o>0;o>>=1){
            if(tid<o){
#pragma unroll
                for(int c=0;c<4;c++) s[c][tid]+=s[c][tid+o];
            }
            __syncthreads();
        }
        if(tid==0 && bid<100){
            const float invP = 1.0f/(float)NPAIR;
            float m1=s[0][0]*invP, q1=s[1][0]*invP;
            float m2=s[2][0]*invP, q2=s[3][0]*invP;
            g_m1[f]=m1; g_s1[f]=rsqrtf(q1-m1*m1+EPSV);
            g_m2[f]=m2; g_s2[f]=rsqrtf(q2-m2*m2+EPSV);
        }
    }
    gridsync(PREPBLK);

    // ---------- P6: fold BN into W1 + folded bias ----------
    {
        int t = bid*512+tid;
        if (t < 6400){
            int o=t&31, f=t>>5;
            float sc = (f<100)? lbng[f]*__ldcg(&g_s1[f]) : lbng[f]*__ldcg(&g_s2[f-100]);
            g_W1p[t] = lw1[o*200+f]*sc;
        }
        if (bid==0 && tid<32){
            int o=tid;
            float c=lb1[o];
            for(int f=0;f<200;f++){
                float m  = (f<100)? __ldcg(&g_m1[f]) : __ldcg(&g_m2[f-100]);
                float sc = (f<100)? lbng[f]*__ldcg(&g_s1[f]) : lbng[f]*__ldcg(&g_s2[f-100]);
                c += lw1[o*200+f]*(lbnb[f]-m*sc);
            }
            g_c[o]=c;
        }
    }
    gridsync(PREPBLK);

    // ---------- P7: per-node projections A,B — 2 warps per node ----------
    {
        float* sWp = (float*)sm_;
        float (*sv)[100]    = (float(*)[100])(sm_+25600);
        float (*spa)[2][32] = (float(*)[2][32])(sm_+28800);
        float (*spb)[2][32] = (float(*)[2][32])(sm_+30848);
        for(int t=tid;t<6400;t+=512) sWp[t]=__ldcg(&g_W1p[t]);
        int n8 = w>>1, h = w&1;
        int node = bid*8 + n8;
        for(int t=lane;t<50;t+=32){
            int f = 50*h + t;
            sv[n8][f]=__ldcg(&g_node[node*100+f]);
        }
        __syncthreads();
        float a=0.f, b=0.f;
        for(int u=0;u<50;u++){
            int f = 50*h+u;
            float v=sv[n8][f];
            a += v*sWp[f*32+lane];
            b += v*sWp[(100+f)*32+lane];
        }
        spa[n8][h][lane]=a; spb[n8][h][lane]=b;
        __syncthreads();
        if (h==0){
            g_A[node*32+lane]=spa[n8][0][lane]+spa[n8][1][lane]+__ldcg(&g_c[lane]);
            g_B[node*32+lane]=spb[n8][0][lane]+spb[n8][1][lane];
        }
    }
}

// =====================================================================
// Pair kernel: tensor cores (m16n8k8 tf32, 3xTF32 split).
// Warp tile = 16 pairs; W2/W3 live entirely in register fragments.
// grid 1023 x 256: 8 warps x 4 tiles x 16 pairs per block.
// =====================================================================
__global__ void __launch_bounds__(256) k_pairs_tc(
        const float* __restrict__ lw2, const float* __restrict__ lb2,
        const float* __restrict__ lw3, const float* __restrict__ lb3,
        float* __restrict__ out){
    const int warp = threadIdx.x>>5, lane = threadIdx.x&31;
    const int g = lane>>2, tig = lane&3;

    // W2 fragments, hi/lo tf32 split: B[k][n]=W2[o][f], o=nt*8+g, k-slice s
    uint32_t Bhi[4][4][2], Blo[4][4][2];
#pragma unroll
    for(int s=0;s<4;s++){
#pragma unroll
        for(int nt=0;nt<4;nt++){
            int o = nt*8 + g;
#pragma unroll
            for(int h=0;h<2;h++){
                float wv = __ldg(&lw2[o*32 + s*8 + tig + 4*h]);
                uint32_t hi = to_tf32(wv);
                Bhi[s][nt][h] = hi;
                Blo[s][nt][h] = to_tf32(wv - __uint_as_float(hi));
            }
        }
    }
    // W3 fragments: cols held by this thread are nt*8+2*tig, +1
    float w3r[2][4][2];
#pragma unroll
    for(int c=0;c<2;c++)
#pragma unroll
        for(int nt=0;nt<4;nt++){
            w3r[c][nt][0]=__ldg(&lw3[c*32+nt*8+2*tig]);
            w3r[c][nt][1]=__ldg(&lw3[c*32+nt*8+2*tig+1]);
        }
    float b2r[4][2];
#pragma unroll
    for(int nt=0;nt<4;nt++){
        b2r[nt][0]=__ldg(&lb2[nt*8+2*tig]);
        b2r[nt][1]=__ldg(&lb2[nt*8+2*tig+1]);
    }
    const float b30=__ldg(&lb3[0]), b31=__ldg(&lb3[1]);

    const int tile0 = (blockIdx.x*8 + warp)*4;
#pragma unroll 1
    for(int tt=0; tt<4; tt++){
        const int base = (tile0+tt)*16;
        // this thread's two pair rows: g and g+8
        int i0,j0,i1,j1;
        {
            int p = base + g;
            int disc=(2*NN-1)*(2*NN-1)-8*p;
            float sqv=sqrtf((float)disc);
            int i=(int)(((float)(2*NN-1)-sqv)*0.5f);
            if(i<0)i=0; if(i>NN-2)i=NN-2;
            while(i<NN-2 && rowstart(i+1)<=p) i++;
            while(i>0 && rowstart(i)>p) i--;
            i0=i; j0=p-rowstart(i)+i+1;
        }
        {
            int p = base + g + 8;
            int disc=(2*NN-1)*(2*NN-1)-8*p;
            float sqv=sqrtf((float)disc);
            int i=(int)(((float)(2*NN-1)-sqv)*0.5f);
            if(i<0)i=0; if(i>NN-2)i=NN-2;
            while(i<NN-2 && rowstart(i+1)<=p) i++;
            while(i>0 && rowstart(i)>p) i--;
            i1=i; j1=p-rowstart(i)+i+1;
        }
        const float* A0r=g_A+i0*32; const float* B0r=g_B+j0*32;
        const float* A1r=g_A+i1*32; const float* B1r=g_B+j1*32;

        float C[4][4];
#pragma unroll
        for(int nt=0;nt<4;nt++){
            C[nt][0]=b2r[nt][0]; C[nt][1]=b2r[nt][1];
            C[nt][2]=b2r[nt][0]; C[nt][3]=b2r[nt][1];
        }

#pragma unroll
        for(int s=0;s<4;s++){
            const int f0=s*8+tig, f1=f0+4;
            float v0 = leaky(A0r[f0]+B0r[f0]);   // a0 = (row g,   col tig)
            float v1 = leaky(A1r[f0]+B1r[f0]);   // a1 = (row g+8, col tig)
            float v2 = leaky(A0r[f1]+B0r[f1]);   // a2 = (row g,   col tig+4)
            float v3 = leaky(A1r[f1]+B1r[f1]);   // a3 = (row g+8, col tig+4)
            uint32_t Ah[4], Al[4];
            Ah[0]=to_tf32(v0); Al[0]=to_tf32(v0-__uint_as_float(Ah[0]));
            Ah[1]=to_tf32(v1); Al[1]=to_tf32(v1-__uint_as_float(Ah[1]));
            Ah[2]=to_tf32(v2); Al[2]=to_tf32(v2-__uint_as_float(Ah[2]));
            Ah[3]=to_tf32(v3); Al[3]=to_tf32(v3-__uint_as_float(Ah[3]));
#pragma unroll
            for(int nt=0;nt<4;nt++){
                mma_tf32(C[nt], Ah, Bhi[s][nt]);
                mma_tf32(C[nt], Ah, Blo[s][nt]);
                mma_tf32(C[nt], Al, Bhi[s][nt]);
            }
        }

        // epilogue: h2 = leaky(C); y = h2 @ W3^T + b3; reduce over tig group
        float y00=0.f,y01=0.f,y10=0.f,y11=0.f;
#pragma unroll
        for(int nt=0;nt<4;nt++){
            float h0=leaky(C[nt][0]), h1v=leaky(C[nt][1]);
            float h2=leaky(C[nt][2]), h3=leaky(C[nt][3]);
            y00 += h0*w3r[0][nt][0] + h1v*w3r[0][nt][1];
            y01 += h0*w3r[1][nt][0] + h1v*w3r[1][nt][1];
            y10 += h2*w3r[0][nt][0] + h3*w3r[0][nt][1];
            y11 += h2*w3r[1][nt][0] + h3*w3r[1][nt][1];
        }
        y00 += __shfl_xor_sync(0xffffffffu,y00,1); y00 += __shfl_xor_sync(0xffffffffu,y00,2);
        y01 += __shfl_xor_sync(0xffffffffu,y01,1); y01 += __shfl_xor_sync(0xffffffffu,y01,2);
        y10 += __shfl_xor_sync(0xffffffffu,y10,1); y10 += __shfl_xor_sync(0xffffffffu,y10,2);
        y11 += __shfl_xor_sync(0xffffffffu,y11,1); y11 += __shfl_xor_sync(0xffffffffu,y11,2);
        if (tig==0){
            *(float2*)(out + (size_t)(base+g)*2)   = make_float2(y00+b30, y01+b31);
            *(float2*)(out + (size_t)(base+g+8)*2) = make_float2(y10+b30, y11+b31);
        }
    }
}

// ---------------- launch: 2 kernels ----------------
extern "C" void kernel_launch(void* const* d_in, const int* in_sizes, int n_in,
                              void* d_out, int out_size){
    const float* feat   = (const float*)d_in[0];
    const float* bn_g   = (const float*)d_in[1];
    const float* bn_b   = (const float*)d_in[2];
    const float* ec1_w1 = (const float*)d_in[3];
    const float* ec1_b1 = (const float*)d_in[4];
    const float* ec1_w2 = (const float*)d_in[5];
    const float* ec1_b2 = (const float*)d_in[6];
    const float* ec2_w1 = (const float*)d_in[7];
    const float* ec2_b1 = (const float*)d_in[8];
    const float* ec2_w2 = (const float*)d_in[9];
    const float* ec2_b2 = (const float*)d_in[10];
    const float* lbn_g  = (const float*)d_in[11];
    const float* lbn_b  = (const float*)d_in[12];
    const float* l_w1   = (const float*)d_in[13];
    const float* l_b1   = (const float*)d_in[14];
    const float* l_w2   = (const float*)d_in[15];
    const float* l_b2   = (const float*)d_in[16];
    const float* l_w3   = (const float*)d_in[17];
    const float* l_b3   = (const float*)d_in[18];
    float* out = (float*)d_out;

    static int attr_done = 0;
    if (!attr_done){
        cudaFuncSetAttribute(k_prep, cudaFuncAttributeMaxDynamicSharedMemorySize, 50176);
        attr_done = 1;
    }

    k_prep <<<PREPBLK, 512, 49152>>>(feat, bn_g, bn_b,
                                     ec1_w1, ec1_b1, ec1_w2, ec1_b2,
                                     ec2_w1, ec2_b1, ec2_w2, ec2_b2,
                                     l_w1, l_b1, lbn_g, lbn_b,
                                     out + (size_t)2*NPAIR);
    // 1023 blocks x 8 warps x 4 tiles x 16 pairs = 523776 pairs exactly
    k_pairs_tc<<<1023, 256>>>(l_w2, l_b2, l_w3, l_b3, out);
}

// round 6
// speedup vs baseline: 1.2912x; 1.1141x over previous
#include <cuda_runtime.h>
#include <math.h>
#include <stdint.h>

#define NN      1024
#define KNN     8
#define D_IN    36
#define NPAIR   (NN*(NN-1)/2)    // 523776
#define EPSV    1e-5f
#define SLOPE   0.01f
#define PREPBLK 128

// ---------------- device scratch ----------------
__device__ float g_node[NN*100];          // [x(36) | e1(32) | e2(32)] per node
__device__ float g_mean[D_IN], g_scale[D_IN];
__device__ float4 g_xy[NN];
__device__ int   g_idx[NN*KNN];
__device__ float4 g_w1t1[72*32];          // ec1_w1 packed: [tt][o]
__device__ float4 g_w1t2[64*32];
__device__ float g_m1[100], g_s1[100], g_m2[100], g_s2[100];
__device__ float g_W1p[200*32];           // BN-scaled l_w1, layout [f][o]
__device__ float g_c[32];
__device__ float g_A[NN*32];
__device__ float g_B[NN*32];
__device__ unsigned int g_bar;

__device__ __forceinline__ float leaky(float x){ return fmaxf(x, SLOPE*x); }
__device__ __forceinline__ int rowstart(int i){ return i*NN - ((i*(i+1))>>1); }

__device__ __forceinline__ void gridsync(unsigned int nblk){
    __threadfence();
    __syncthreads();
    if (threadIdx.x == 0){
        unsigned int t = atomicAdd(&g_bar, 1u);
        unsigned int target = t - (t % nblk) + nblk;
        volatile unsigned int* vb = &g_bar;
        while (*vb < target) {}
        __threadfence();
    }
    __syncthreads();
}

// tf32 helpers
__device__ __forceinline__ uint32_t to_tf32(float v){
    uint32_t r; asm("cvt.rna.tf32.f32 %0,%1;":"=r"(r):"f"(v)); return r;
}
__device__ __forceinline__ void mma_tf32(float* C, const uint32_t* A, const uint32_t* B){
    asm volatile(
      "mma.sync.aligned.m16n8k8.row.col.f32.tf32.tf32.f32 "
      "{%0,%1,%2,%3},{%4,%5,%6,%7},{%8,%9},{%0,%1,%2,%3};"
      : "+f"(C[0]),"+f"(C[1]),"+f"(C[2]),"+f"(C[3])
      : "r"(A[0]),"r"(A[1]),"r"(A[2]),"r"(A[3]),"r"(B[0]),"r"(B[1]));
}

// =====================================================================
// Persistent prep kernel: 8 phases, 128 blocks x 512 threads (unchanged)
// =====================================================================
__global__ void __launch_bounds__(512) k_prep(
        const float* __restrict__ feat,
        const float* __restrict__ bng,  const float* __restrict__ bnb,
        const float* __restrict__ e1w1, const float* __restrict__ e1b1,
        const float* __restrict__ e1w2, const float* __restrict__ e1b2,
        const float* __restrict__ e2w1, const float* __restrict__ e2b1,
        const float* __restrict__ e2w2, const float* __restrict__ e2b2,
        const float* __restrict__ lw1,  const float* __restrict__ lb1,
        const float* __restrict__ lbng, const float* __restrict__ lbnb,
        float* __restrict__ out_cells){
    extern __shared__ char sm_[];
    const int tid = threadIdx.x;
    const int bid = blockIdx.x;
    const int w   = tid>>5, lane = tid&31;

    // ---------- P0: BN stats (blocks 0..35) | weight pack (36..71) ----------
    if (bid < 36){
        int f = bid;
        float* ss = (float*)sm_;
        float* sq = ss+512;
        float s=0.f, q=0.f;
        for(int i=tid;i<NN;i+=512){ float v=feat[i*D_IN+f]; s+=v; q+=v*v; }
        ss[tid]=s; sq[tid]=q; __syncthreads();
        for(int o=256;o>0;o>>=1){
            if(tid<o){ ss[tid]+=ss[tid+o]; sq[tid]+=sq[tid+o]; }
            __syncthreads();
        }
        if(tid==0){
            float m=ss[0]*(1.f/NN);
            float var=sq[0]*(1.f/NN)-m*m;
            g_mean[f]=m; g_scale[f]=rsqrtf(var+EPSV);
        }
    } else if (bid < 72){
        int t = (bid-36)*512 + tid;
        if (t < 72*32){ int tt=t>>5, o=t&31; g_w1t1[t] = *(const float4*)(e1w1 + o*288 + 4*tt); }
        if (t < 64*32){ int tt=t>>5, o=t&31; g_w1t2[t] = *(const float4*)(e2w1 + o*256 + 4*tt); }
    }
    gridsync(PREPBLK);

    // ---------- P1: normalize + cells + compact coords ----------
    {
        int t = bid*512 + tid;
        if (t < NN*D_IN){
            int i=t/D_IN, f=t%D_IN;
            float v = (feat[t]-__ldcg(&g_mean[f]))*__ldcg(&g_scale[f])*bng[f]+bnb[f];
            g_node[i*100+f] = v;
            if (f < 4) ((float*)g_xy)[i*4+f] = v;
        }
        if (t < NN*5){
            int i=t/5, c=t%5;
            out_cells[i*5+c] = feat[i*D_IN+c];
        }
    }
    gridsync(PREPBLK);

    // ---------- P2: kNN, 2 warps per node ----------
    {
        float4* sxy = (float4*)sm_;
        float  (*skd)[2][8] = (float(*)[2][8])(sm_+16384);
        int    (*ski)[2][8] = (int  (*)[2][8])(sm_+16384+512);
        for(int t=tid;t<NN;t+=512) sxy[t] = __ldcg(&g_xy[t]);
        __syncthreads();

        int n8 = w>>1, h = w&1;
        int node = bid*8 + n8;
        const float4 xi = sxy[node];

        float d8[8]; int id8[8];
#pragma unroll
        for(int k=0;k<8;k++){ d8[k]=3.4e38f; id8[k]=0x7fffffff; }
        float kth = 3.4e38f; int kthi = 0x7fffffff;
        for(int it=0; it<16; it++){
            int j = 512*h + it*32 + lane;
            float4 xj = sxy[j];
            float cd = fabsf(xi.x-xj.x)+fabsf(xi.y-xj.y)+fabsf(xi.z-xj.z)+fabsf(xi.w-xj.w);
            int ci = j;
            if (cd < kth || (cd==kth && ci < kthi)){
#pragma unroll
                for(int k=0;k<8;k++){
                    bool sw = (cd < d8[k]) || (cd==d8[k] && ci < id8[k]);
                    float td = sw ? d8[k] : cd; int ti = sw ? id8[k] : ci;
                    d8[k]  = sw ? cd : d8[k]; id8[k] = sw ? ci : id8[k];
                    cd=td; ci=ti;
                }
                kth = d8[7]; kthi = id8[7];
            }
        }
        for(int r=0;r<8;r++){
            float bd=d8[0]; int bi=id8[0];
#pragma unroll
            for(int off=16;off>0;off>>=1){
                float od=__shfl_xor_sync(0xffffffffu,bd,off);
                int   oi=__shfl_xor_sync(0xffffffffu,bi,off);
                if (od<bd || (od==bd && oi<bi)){ bd=od; bi=oi; }
            }
            if (lane==0){ skd[n8][h][r]=bd; ski[n8][h][r]=bi; }
            if (id8[0]==bi){
#pragma unroll
                for(int k=0;k<7;k++){ d8[k]=d8[k+1]; id8[k]=id8[k+1]; }
                d8[7]=3.4e38f; id8[7]=0x7fffffff;
            }
        }
        __syncthreads();
        if (h==0){
            float md = 3.4e38f; int mi = 0x7fffffff;
            if (lane < 16){ md = skd[n8][lane>>3][lane&7]; mi = ski[n8][lane>>3][lane&7]; }
            for(int r=0;r<8;r++){
                float bd=md; int bi=mi;
#pragma unroll
                for(int off=16;off>0;off>>=1){
                    float od=__shfl_xor_sync(0xffffffffu,bd,off);
                    int   oi=__shfl_xor_sync(0xffffffffu,bi,off);
                    if (od<bd || (od==bd && oi<bi)){ bd=od; bi=oi; }
                }
                if (lane==0) g_idx[node*KNN+r]=bi;
                if (md==bd && mi==bi){ md=3.4e38f; mi=0x7fffffff; }
            }
        }
    }
    gridsync(PREPBLK);

    // ---------- P3: edge conv 1, 2 warps per node ----------
    {
        float4* sW  = (float4*)sm_;
        float (*sv)[288]   = (float(*)[288])(sm_+36864);
        float (*sh2)[2][32]= (float(*)[2][32])(sm_+46080);
        float (*sh1)[32]   = (float(*)[32])(sm_+48128);
        for(int t=tid;t<72*32;t+=512) sW[t]=__ldcg(&g_w1t1[t]);
        int n8 = w>>1, h = w&1;
        int node = bid*8 + n8;
        for(int t=lane;t<144;t+=32){
            int f = 18*h + (t>>3), k = t&7;
            int nb = __ldcg(&g_idx[node*KNN+k]);
            sv[n8][f*8+k] = __ldcg(&g_node[nb*100+f]);
        }
        __syncthreads();
        float a0=0.f,a1=0.f,a2=0.f,a3=0.f;
        const float4* vv4 = (const float4*)sv[n8];
#pragma unroll
        for(int u=0;u<36;u++){
            int tt = 36*h+u;
            float4 wv = sW[tt*32+lane];
            float4 vv = vv4[tt];
            a0+=wv.x*vv.x; a1+=wv.y*vv.y; a2+=wv.z*vv.z; a3+=wv.w*vv.w;
        }
        sh2[n8][h][lane]=((a0+a1)+(a2+a3));
        __syncthreads();
        if (h==0){
            float acc = sh2[n8][0][lane]+sh2[n8][1][lane]+e1b1[lane];
            sh1[n8][lane]=leaky(acc);
            __syncwarp();
            float acc2 = e1b2[lane];
            const float4* w2v = (const float4*)(e1w2 + lane*32);
#pragma unroll
            for(int q=0;q<8;q++){
                float4 wv=w2v[q];
                acc2 += wv.x*sh1[n8][4*q]+wv.y*sh1[n8][4*q+1]+wv.z*sh1[n8][4*q+2]+wv.w*sh1[n8][4*q+3];
            }
            g_node[node*100+36+lane]=leaky(acc2);
        }
    }
    gridsync(PREPBLK);

    // ---------- P4: edge conv 2, 2 warps per node ----------
    {
        float4* sW  = (float4*)sm_;
        float (*sv)[256]   = (float(*)[256])(sm_+32768);
        float (*sh2)[2][32]= (float(*)[2][32])(sm_+40960);
        float (*sh1)[32]   = (float(*)[32])(sm_+43008);
        for(int t=tid;t<64*32;t+=512) sW[t]=__ldcg(&g_w1t2[t]);
        int n8 = w>>1, h = w&1;
        int node = bid*8 + n8;
        for(int t=lane;t<128;t+=32){
            int f = 16*h + (t>>3), k = t&7;
            int nb = __ldcg(&g_idx[node*KNN+k]);
            sv[n8][f*8+k] = __ldcg(&g_node[nb*100+36+f]);
        }
        __syncthreads();
        float a0=0.f,a1=0.f,a2=0.f,a3=0.f;
        const float4* vv4 = (const float4*)sv[n8];
#pragma unroll
        for(int u=0;u<32;u++){
            int tt = 32*h+u;
            float4 wv = sW[tt*32+lane];
            float4 vv = vv4[tt];
            a0+=wv.x*vv.x; a1+=wv.y*vv.y; a2+=wv.z*vv.z; a3+=wv.w*vv.w;
        }
        sh2[n8][h][lane]=((a0+a1)+(a2+a3));
        __syncthreads();
        if (h==0){
            float acc = sh2[n8][0][lane]+sh2[n8][1][lane]+e2b1[lane];
            sh1[n8][lane]=leaky(acc);
            __syncwarp();
            float acc2 = e2b2[lane];
            const float4* w2v = (const float4*)(e2w2 + lane*32);
#pragma unroll
            for(int q=0;q<8;q++){
                float4 wv=w2v[q];
                acc2 += wv.x*sh1[n8][4*q]+wv.y*sh1[n8][4*q+1]+wv.z*sh1[n8][4*q+2]+wv.w*sh1[n8][4*q+3];
            }
            g_node[node*100+68+lane]=leaky(acc2);
        }
    }
    gridsync(PREPBLK);

    // ---------- P5: pair-BN stats via weighted node moments ----------
    {
        int f = (bid < 100) ? bid : 0;
        float (*s)[512] = (float(*)[512])sm_;
        float sa=0,qa=0,sb=0,qb=0;
        for(int i=tid;i<NN;i+=512){
            float v=__ldcg(&g_node[i*100+f]);
            float wa=(float)(NN-1-i), wb=(float)i;
            sa+=wa*v; qa+=wa*v*v; sb+=wb*v; qb+=wb*v*v;
        }
        s[0][tid]=sa; s[1][tid]=qa; s[2][tid]=sb; s[3][tid]=qb;
        __syncthreads();
        for(int o=256;o>0;o>>=1){
            if(tid<o){
#pragma unroll
                for(int c=0;c<4;c++) s[c][tid]+=s[c][tid+o];
            }
            __syncthreads();
        }
        if(tid==0 && bid<100){
            const float invP = 1.0f/(float)NPAIR;
            float m1=s[0][0]*invP, q1=s[1][0]*invP;
            float m2=s[2][0]*invP, q2=s[3][0]*invP;
            g_m1[f]=m1; g_s1[f]=rsqrtf(q1-m1*m1+EPSV);
            g_m2[f]=m2; g_s2[f]=rsqrtf(q2-m2*m2+EPSV);
        }
    }
    gridsync(PREPBLK);

    // ---------- P6: fold BN into W1 + folded bias ----------
    {
        int t = bid*512+tid;
        if (t < 6400){
            int o=t&31, f=t>>5;
            float sc = (f<100)? lbng[f]*__ldcg(&g_s1[f]) : lbng[f]*__ldcg(&g_s2[f-100]);
            g_W1p[t] = lw1[o*200+f]*sc;
        }
        if (bid==0 && tid<32){
            int o=tid;
            float c=lb1[o];
            for(int f=0;f<200;f++){
                float m  = (f<100)? __ldcg(&g_m1[f]) : __ldcg(&g_m2[f-100]);
                float sc = (f<100)? lbng[f]*__ldcg(&g_s1[f]) : lbng[f]*__ldcg(&g_s2[f-100]);
                c += lw1[o*200+f]*(lbnb[f]-m*sc);
            }
            g_c[o]=c;
        }
    }
    gridsync(PREPBLK);

    // ---------- P7: per-node projections A,B — 2 warps per node ----------
    {
        float* sWp = (float*)sm_;
        float (*sv)[100]    = (float(*)[100])(sm_+25600);
        float (*spa)[2][32] = (float(*)[2][32])(sm_+28800);
        float (*spb)[2][32] = (float(*)[2][32])(sm_+30848);
        for(int t=tid;t<6400;t+=512) sWp[t]=__ldcg(&g_W1p[t]);
        int n8 = w>>1, h = w&1;
        int node = bid*8 + n8;
        for(int t=lane;t<50;t+=32){
            int f = 50*h + t;
            sv[n8][f]=__ldcg(&g_node[node*100+f]);
        }
        __syncthreads();
        float a=0.f, b=0.f;
        for(int u=0;u<50;u++){
            int f = 50*h+u;
            float v=sv[n8][f];
            a += v*sWp[f*32+lane];
            b += v*sWp[(100+f)*32+lane];
        }
        spa[n8][h][lane]=a; spb[n8][h][lane]=b;
        __syncthreads();
        if (h==0){
            g_A[node*32+lane]=spa[n8][0][lane]+spa[n8][1][lane]+__ldcg(&g_c[lane]);
            g_B[node*32+lane]=spb[n8][0][lane]+spb[n8][1][lane];
        }
    }
}

// =====================================================================
// Pair kernel v2: cooperative SMEM staging of h1 + tensor cores.
// Warp tile = 16 pairs. grid 1023 x 256: 8 warps x 4 tiles x 16 pairs.
// =====================================================================
#define H1STRIDE 40
__global__ void __launch_bounds__(256,2) k_pairs_tc(
        const float* __restrict__ lw2, const float* __restrict__ lb2,
        const float* __restrict__ lw3, const float* __restrict__ lb3,
        float* __restrict__ out){
    __shared__ float sh1s[8][16*H1STRIDE];    // per-warp h1 staging (20 KB)
    __shared__ float sW3[64], sB2[32], sB3[2];
    const int warp = threadIdx.x>>5, lane = threadIdx.x&31;
    const int g = lane>>2, tig = lane&3;

    if (threadIdx.x<64) sW3[threadIdx.x]=lw3[threadIdx.x];
    if (threadIdx.x<32) sB2[threadIdx.x]=lb2[threadIdx.x];
    if (threadIdx.x<2)  sB3[threadIdx.x]=lb3[threadIdx.x];
    __syncthreads();

    // W2 fragments, hi/lo tf32 split: B[k][n]=W2[o][f], o=nt*8+g, k-slice s
    uint32_t Bhi[4][4][2], Blo[4][4][2];
#pragma unroll
    for(int s=0;s<4;s++){
#pragma unroll
        for(int nt=0;nt<4;nt++){
            int o = nt*8 + g;
#pragma unroll
            for(int h=0;h<2;h++){
                float wv = __ldg(&lw2[o*32 + s*8 + tig + 4*h]);
                uint32_t hi = to_tf32(wv);
                Bhi[s][nt][h] = hi;
                Blo[s][nt][h] = to_tf32(wv - __uint_as_float(hi));
            }
        }
    }

    float* sh = sh1s[warp];
    const int pr = lane>>1, half = lane&1;
    const int tile0 = (blockIdx.x*8 + warp)*4;

#pragma unroll 1
    for(int tt=0; tt<4; tt++){
        const int base = (tile0+tt)*16;

        // ---- stage h1[16][32] cooperatively: lane -> (pair pr, half) ----
        {
            int p = base + pr;
            int disc=(2*NN-1)*(2*NN-1)-8*p;
            float sqv=sqrtf((float)disc);
            int i=(int)(((float)(2*NN-1)-sqv)*0.5f);
            if(i<0)i=0; if(i>NN-2)i=NN-2;
            while(i<NN-2 && rowstart(i+1)<=p) i++;
            while(i>0 && rowstart(i)>p) i--;
            int j = p-rowstart(i)+i+1;
            const float4* a4 = (const float4*)(g_A + i*32 + half*16);
            const float4* b4 = (const float4*)(g_B + j*32 + half*16);
            float4* row = (float4*)(sh + pr*H1STRIDE + half*16);
#pragma unroll
            for(int q=0;q<4;q++){
                float4 av=a4[q], bv=b4[q];
                float4 hv;
                hv.x=leaky(av.x+bv.x); hv.y=leaky(av.y+bv.y);
                hv.z=leaky(av.z+bv.z); hv.w=leaky(av.w+bv.w);
                row[q]=hv;
            }
        }
        __syncwarp();

        // ---- MMA: C[16][32] = h1 @ W2^T  (3xTF32 split) ----
        float C[4][4];
        {
            float c0=sB2[8*0+2*tig], c1=sB2[8*0+2*tig+1];
            C[0][0]=c0; C[0][1]=c1; C[0][2]=c0; C[0][3]=c1;
        }
#pragma unroll
        for(int nt=1;nt<4;nt++){
            float c0=sB2[nt*8+2*tig], c1=sB2[nt*8+2*tig+1];
            C[nt][0]=c0; C[nt][1]=c1; C[nt][2]=c0; C[nt][3]=c1;
        }
#pragma unroll
        for(int s=0;s<4;s++){
            const int f0=s*8+tig, f1=f0+4;
            float v0 = sh[ g   *H1STRIDE + f0];
            float v1 = sh[(g+8)*H1STRIDE + f0];
            float v2 = sh[ g   *H1STRIDE + f1];
            float v3 = sh[(g+8)*H1STRIDE + f1];
            uint32_t Ah[4], Al[4];
            Ah[0]=to_tf32(v0); Al[0]=to_tf32(v0-__uint_as_float(Ah[0]));
            Ah[1]=to_tf32(v1); Al[1]=to_tf32(v1-__uint_as_float(Ah[1]));
            Ah[2]=to_tf32(v2); Al[2]=to_tf32(v2-__uint_as_float(Ah[2]));
            Ah[3]=to_tf32(v3); Al[3]=to_tf32(v3-__uint_as_float(Ah[3]));
#pragma unroll
            for(int nt=0;nt<4;nt++){
                mma_tf32(C[nt], Ah, Bhi[s][nt]);
                mma_tf32(C[nt], Ah, Blo[s][nt]);
                mma_tf32(C[nt], Al, Bhi[s][nt]);
            }
        }

        // ---- epilogue: h2=leaky(C); y = h2 @ W3^T + b3 ----
        float y00=0.f,y01=0.f,y10=0.f,y11=0.f;
#pragma unroll
        for(int nt=0;nt<4;nt++){
            float w300=sW3[nt*8+2*tig],    w301=sW3[nt*8+2*tig+1];
            float w310=sW3[32+nt*8+2*tig], w311=sW3[32+nt*8+2*tig+1];
            float h0=leaky(C[nt][0]), h1v=leaky(C[nt][1]);
            float h2=leaky(C[nt][2]), h3=leaky(C[nt][3]);
            y00 += h0*w300 + h1v*w301;
            y01 += h0*w310 + h1v*w311;
            y10 += h2*w300 + h3*w301;
            y11 += h2*w310 + h3*w311;
        }
        y00 += __shfl_xor_sync(0xffffffffu,y00,1); y00 += __shfl_xor_sync(0xffffffffu,y00,2);
        y01 += __shfl_xor_sync(0xffffffffu,y01,1); y01 += __shfl_xor_sync(0xffffffffu,y01,2);
        y10 += __shfl_xor_sync(0xffffffffu,y10,1); y10 += __shfl_xor_sync(0xffffffffu,y10,2);
        y11 += __shfl_xor_sync(0xffffffffu,y11,1); y11 += __shfl_xor_sync(0xffffffffu,y11,2);
        if (tig==0){
            *(float2*)(out + (size_t)(base+g)*2)   = make_float2(y00+sB3[0], y01+sB3[1]);
            *(float2*)(out + (size_t)(base+g+8)*2) = make_float2(y10+sB3[0], y11+sB3[1]);
        }
        __syncwarp();   // staging buffer reuse safety
    }
}

// ---------------- launch: 2 kernels ----------------
extern "C" void kernel_launch(void* const* d_in, const int* in_sizes, int n_in,
                              void* d_out, int out_size){
    const float* feat   = (const float*)d_in[0];
    const float* bn_g   = (const float*)d_in[1];
    const float* bn_b   = (const float*)d_in[2];
    const float* ec1_w1 = (const float*)d_in[3];
    const float* ec1_b1 = (const float*)d_in[4];
    const float* ec1_w2 = (const float*)d_in[5];
    const float* ec1_b2 = (const float*)d_in[6];
    const float* ec2_w1 = (const float*)d_in[7];
    const float* ec2_b1 = (const float*)d_in[8];
    const float* ec2_w2 = (const float*)d_in[9];
    const float* ec2_b2 = (const float*)d_in[10];
    const float* lbn_g  = (const float*)d_in[11];
    const float* lbn_b  = (const float*)d_in[12];
    const float* l_w1   = (const float*)d_in[13];
    const float* l_b1   = (const float*)d_in[14];
    const float* l_w2   = (const float*)d_in[15];
    const float* l_b2   = (const float*)d_in[16];
    const float* l_w3   = (const float*)d_in[17];
    const float* l_b3   = (const float*)d_in[18];
    float* out = (float*)d_out;

    static int attr_done = 0;
    if (!attr_done){
        cudaFuncSetAttribute(k_prep, cudaFuncAttributeMaxDynamicSharedMemorySize, 50176);
        attr_done = 1;
    }

    k_prep <<<PREPBLK, 512, 49152>>>(feat, bn_g, bn_b,
                                     ec1_w1, ec1_b1, ec1_w2, ec1_b2,
                                     ec2_w1, ec2_b1, ec2_w2, ec2_b2,
                                     l_w1, l_b1, lbn_g, lbn_b,
                                     out + (size_t)2*NPAIR);
    // 1023 blocks x 8 warps x 4 tiles x 16 pairs = 523776 pairs exactly
    k_pairs_tc<<<1023, 256>>>(l_w2, l_b2, l_w3, l_b3, out);
}

// round 7
// speedup vs baseline: 1.7275x; 1.3379x over previous
#include <cuda_runtime.h>
#include <math.h>
#include <stdint.h>

#define NN      1024
#define KNN     8
#define D_IN    36
#define NPAIR   (NN*(NN-1)/2)    // 523776
#define EPSV    1e-5f
#define SLOPE   0.01f
#define TAILBLK 128

// ---------------- device scratch ----------------
__device__ float g_x[NN*36];              // normalized features
__device__ float g_e1[NN*32];             // edge conv 1 out (128B rows)
__device__ float g_e2[NN*32];             // edge conv 2 out (128B rows)
__device__ float g_mean[D_IN], g_scale[D_IN];
__device__ float4 g_xy[NN];
__device__ int   g_idx[NN*KNN];
__device__ float4 g_w1t1[72*32];          // ec1_w1 packed: [tt][o]
__device__ float4 g_w1t2[64*32];
__device__ float g_part[4*100*128];       // 2-stage pair-stats partials
__device__ float g_m1[100], g_s1[100], g_m2[100], g_s2[100];
__device__ float g_A[NN*32];
__device__ float g_B[NN*32];
__device__ unsigned int g_bar;

__device__ __forceinline__ float leaky(float x){ return fmaxf(x, SLOPE*x); }
__device__ __forceinline__ int rowstart(int i){ return i*NN - ((i*(i+1))>>1); }

__device__ __forceinline__ void gridsync(unsigned int nblk){
    __threadfence();
    __syncthreads();
    if (threadIdx.x == 0){
        unsigned int t = atomicAdd(&g_bar, 1u);
        unsigned int target = t - (t % nblk) + nblk;
        volatile unsigned int* vb = &g_bar;
        while (*vb < target) {}
        __threadfence();
    }
    __syncthreads();
}

// tf32 helpers
__device__ __forceinline__ uint32_t to_tf32(float v){
    uint32_t r; asm("cvt.rna.tf32.f32 %0,%1;":"=r"(r):"f"(v)); return r;
}
__device__ __forceinline__ void mma_tf32(float* C, const uint32_t* A, const uint32_t* B){
    asm volatile(
      "mma.sync.aligned.m16n8k8.row.col.f32.tf32.tf32.f32 "
      "{%0,%1,%2,%3},{%4,%5,%6,%7},{%8,%9},{%0,%1,%2,%3};"
      : "+f"(C[0]),"+f"(C[1]),"+f"(C[2]),"+f"(C[3])
      : "r"(A[0]),"r"(A[1]),"r"(A[2]),"r"(A[3]),"r"(B[0]),"r"(B[1]));
}

// ============ k1: BN stats (blocks 0..35) + weight pack (36..71) ============
__global__ void __launch_bounds__(512) k_stats(const float* __restrict__ feat,
        const float* __restrict__ e1w1, const float* __restrict__ e2w1){
    __shared__ float ss[512], sq[512];
    int tid=threadIdx.x, bid=blockIdx.x;
    if (bid < 36){
        int f = bid;
        float s=0.f, q=0.f;
        for(int i=tid;i<NN;i+=512){ float v=feat[i*D_IN+f]; s+=v; q+=v*v; }
        ss[tid]=s; sq[tid]=q; __syncthreads();
        for(int o=256;o>0;o>>=1){
            if(tid<o){ ss[tid]+=ss[tid+o]; sq[tid]+=sq[tid+o]; }
            __syncthreads();
        }
        if(tid==0){
            float m=ss[0]*(1.f/NN);
            float var=sq[0]*(1.f/NN)-m*m;
            g_mean[f]=m; g_scale[f]=rsqrtf(var+EPSV);
        }
    } else {
        int t = (bid-36)*512 + tid;
        if (t < 72*32){ int tt=t>>5, o=t&31; g_w1t1[t] = *(const float4*)(e1w1 + o*288 + 4*tt); }
        if (t < 64*32){ int tt=t>>5, o=t&31; g_w1t2[t] = *(const float4*)(e2w1 + o*256 + 4*tt); }
    }
}

// ============ k2: normalize + cells + compact coords (72 x 512) ============
__global__ void __launch_bounds__(512) k_norm(const float* __restrict__ feat,
        const float* __restrict__ bng, const float* __restrict__ bnb,
        float* __restrict__ out_cells){
    int t = blockIdx.x*512 + threadIdx.x;   // covers 36864 = NN*D_IN exactly
    int i=t/D_IN, f=t%D_IN;
    float v = (feat[t]-g_mean[f])*g_scale[f]*bng[f]+bnb[f];
    g_x[i*D_IN+f] = v;
    if (f < 4) ((float*)g_xy)[i*4+f] = v;
    if (t < NN*5){
        int ii=t/5, c=t%5;
        out_cells[ii*5+c] = feat[ii*D_IN+c];
    }
}

// ============ k3: kNN + edge conv 1 fused (128 x 512) ============
__global__ void __launch_bounds__(512) k_knn_e1(const float* __restrict__ b1,
        const float* __restrict__ w2, const float* __restrict__ b2){
    extern __shared__ char sm_[];
    const int tid=threadIdx.x, bid=blockIdx.x;
    const int w=tid>>5, lane=tid&31;
    const int n8=w>>1, h=w&1;
    const int node = bid*8 + n8;

    // ---- kNN (2 warps per node) ----
    {
        float4* sxy = (float4*)sm_;                        // 16384
        float  (*skd)[2][8] = (float(*)[2][8])(sm_+16384); // 512
        int    (*ski)[2][8] = (int  (*)[2][8])(sm_+16896); // 512
        for(int t=tid;t<NN;t+=512) sxy[t] = g_xy[t];
        __syncthreads();
        const float4 xi = sxy[node];
        float d8[8]; int id8[8];
#pragma unroll
        for(int k=0;k<8;k++){ d8[k]=3.4e38f; id8[k]=0x7fffffff; }
        float kth = 3.4e38f; int kthi = 0x7fffffff;
        for(int it=0; it<16; it++){
            int j = 512*h + it*32 + lane;
            float4 xj = sxy[j];
            float cd = fabsf(xi.x-xj.x)+fabsf(xi.y-xj.y)+fabsf(xi.z-xj.z)+fabsf(xi.w-xj.w);
            int ci = j;
            if (cd < kth || (cd==kth && ci < kthi)){
#pragma unroll
                for(int k=0;k<8;k++){
                    bool sw = (cd < d8[k]) || (cd==d8[k] && ci < id8[k]);
                    float td = sw ? d8[k] : cd; int ti = sw ? id8[k] : ci;
                    d8[k]  = sw ? cd : d8[k]; id8[k] = sw ? ci : id8[k];
                    cd=td; ci=ti;
                }
                kth = d8[7]; kthi = id8[7];
            }
        }
        for(int r=0;r<8;r++){
            float bd=d8[0]; int bi=id8[0];
#pragma unroll
            for(int off=16;off>0;off>>=1){
                float od=__shfl_xor_sync(0xffffffffu,bd,off);
                int   oi=__shfl_xor_sync(0xffffffffu,bi,off);
                if (od<bd || (od==bd && oi<bi)){ bd=od; bi=oi; }
            }
            if (lane==0){ skd[n8][h][r]=bd; ski[n8][h][r]=bi; }
            if (id8[0]==bi){
#pragma unroll
                for(int k=0;k<7;k++){ d8[k]=d8[k+1]; id8[k]=id8[k+1]; }
                d8[7]=3.4e38f; id8[7]=0x7fffffff;
            }
        }
        __syncthreads();
        if (h==0){
            float md = 3.4e38f; int mi = 0x7fffffff;
            if (lane < 16){ md = skd[n8][lane>>3][lane&7]; mi = ski[n8][lane>>3][lane&7]; }
            for(int r=0;r<8;r++){
                float bd=md; int bi=mi;
#pragma unroll
                for(int off=16;off>0;off>>=1){
                    float od=__shfl_xor_sync(0xffffffffu,bd,off);
                    int   oi=__shfl_xor_sync(0xffffffffu,bi,off);
                    if (od<bd || (od==bd && oi<bi)){ bd=od; bi=oi; }
                }
                if (lane==0) g_idx[node*KNN+r]=bi;
                if (md==bd && mi==bi){ md=3.4e38f; mi=0x7fffffff; }
            }
        }
    }
    __syncthreads();

    // ---- edge conv 1 ----
    {
        float4* sW  = (float4*)sm_;                         // 36864
        float (*sv)[288]   = (float(*)[288])(sm_+36864);    // 9216
        float (*sh2)[2][32]= (float(*)[2][32])(sm_+46080);  // 2048
        float (*sh1)[32]   = (float(*)[32])(sm_+48128);     // 1024
        for(int t=tid;t<72*32;t+=512) sW[t]=g_w1t1[t];
        for(int t=lane;t<144;t+=32){
            int f = 18*h + (t>>3), k = t&7;
            int nb = g_idx[node*KNN+k];
            sv[n8][f*8+k] = g_x[nb*D_IN+f];
        }
        __syncthreads();
        float a0=0.f,a1=0.f,a2=0.f,a3=0.f;
        const float4* vv4 = (const float4*)sv[n8];
#pragma unroll
        for(int u=0;u<36;u++){
            int tt = 36*h+u;
            float4 wv = sW[tt*32+lane];
            float4 vv = vv4[tt];
            a0+=wv.x*vv.x; a1+=wv.y*vv.y; a2+=wv.z*vv.z; a3+=wv.w*vv.w;
        }
        sh2[n8][h][lane]=((a0+a1)+(a2+a3));
        __syncthreads();
        if (h==0){
            float acc = sh2[n8][0][lane]+sh2[n8][1][lane]+b1[lane];
            sh1[n8][lane]=leaky(acc);
            __syncwarp();
            float acc2 = b2[lane];
            const float4* w2v = (const float4*)(w2 + lane*32);
#pragma unroll
            for(int q=0;q<8;q++){
                float4 wv=w2v[q];
                acc2 += wv.x*sh1[n8][4*q]+wv.y*sh1[n8][4*q+1]+wv.z*sh1[n8][4*q+2]+wv.w*sh1[n8][4*q+3];
            }
            g_e1[node*32+lane]=leaky(acc2);
        }
    }
}

// ============ k4: edge2 -> pair stats (2-stage) -> W1p/c -> A,B ============
__global__ void __launch_bounds__(512) k_tail2(
        const float* __restrict__ b1, const float* __restrict__ w2,
        const float* __restrict__ b2,
        const float* __restrict__ lw1, const float* __restrict__ lb1,
        const float* __restrict__ lbng, const float* __restrict__ lbnb){
    extern __shared__ char sm_[];
    const int tid=threadIdx.x, bid=blockIdx.x;
    const int w=tid>>5, lane=tid&31;
    const int n8=w>>1, h=w&1;
    const int node = bid*8 + n8;

    // ---- A: edge conv 2 ----
    {
        float4* sW  = (float4*)sm_;                         // 32768
        float (*sv)[256]   = (float(*)[256])(sm_+32768);    // 8192
        float (*sh2)[2][32]= (float(*)[2][32])(sm_+40960);  // 2048
        float (*sh1)[32]   = (float(*)[32])(sm_+43008);     // 1024
        for(int t=tid;t<64*32;t+=512) sW[t]=g_w1t2[t];
        for(int t=lane;t<128;t+=32){
            int f = 16*h + (t>>3), k = t&7;
            int nb = g_idx[node*KNN+k];
            sv[n8][f*8+k] = g_e1[nb*32+f];
        }
        __syncthreads();
        float a0=0.f,a1=0.f,a2=0.f,a3=0.f;
        const float4* vv4 = (const float4*)sv[n8];
#pragma unroll
        for(int u=0;u<32;u++){
            int tt = 32*h+u;
            float4 wv = sW[tt*32+lane];
            float4 vv = vv4[tt];
            a0+=wv.x*vv.x; a1+=wv.y*vv.y; a2+=wv.z*vv.z; a3+=wv.w*vv.w;
        }
        sh2[n8][h][lane]=((a0+a1)+(a2+a3));
        __syncthreads();
        if (h==0){
            float acc = sh2[n8][0][lane]+sh2[n8][1][lane]+b1[lane];
            sh1[n8][lane]=leaky(acc);
            __syncwarp();
            float acc2 = b2[lane];
            const float4* w2v = (const float4*)(w2 + lane*32);
#pragma unroll
            for(int q=0;q<8;q++){
                float4 wv=w2v[q];
                acc2 += wv.x*sh1[n8][4*q]+wv.y*sh1[n8][4*q+1]+wv.z*sh1[n8][4*q+2]+wv.w*sh1[n8][4*q+3];
            }
            g_e2[node*32+lane]=leaky(acc2);
        }
    }
    __syncthreads();

    // ---- B: stats stage 1 — per-block (8 nodes) weighted partials ----
    {
        float (*srow)[100] = (float(*)[100])sm_;    // 8 x 100 floats
        // load own 8 nodes' [x|e1|e2] rows (coalesced-ish)
        for(int t=tid;t<288;t+=512) srow[t/36][t%36]      = g_x [bid*8*36 + t];
        for(int t=tid;t<256;t+=512) srow[t>>5][36+(t&31)] = g_e1[bid*8*32 + t];
        for(int t=tid;t<256;t+=512) srow[t>>5][68+(t&31)] = g_e2[bid*8*32 + t];
        __syncthreads();
        if (tid < 400){
            int c = tid/100, f = tid%100;
            float acc=0.f;
#pragma unroll
            for(int nd=0;nd<8;nd++){
                int gi = bid*8+nd;
                float v = srow[nd][f];
                float wt = (c<2)? (float)(NN-1-gi) : (float)gi;
                float vv = (c&1)? v*v : v;
                acc += wt*vv;
            }
            g_part[(c*100+f)*128 + bid] = acc;
        }
    }
    gridsync(TAILBLK);

    // ---- C: stats stage 2 — reduce 128 partials per (c,f) ----
    {
        float* red = (float*)sm_;      // 512 floats
        int f = (bid<100)? bid : 0;
        int c = tid>>7, idx = tid&127;
        red[tid] = __ldcg(&g_part[(c*100+f)*128 + idx]);
        __syncthreads();
        for(int o=64;o>0;o>>=1){
            if ((tid&127) < o) red[tid] += red[tid+o];
            __syncthreads();
        }
        if (tid==0 && bid<100){
            const float invP = 1.0f/(float)NPAIR;
            float m1=red[0]*invP,   q1=red[128]*invP;
            float m2=red[256]*invP, q2=red[384]*invP;
            g_m1[f]=m1; g_s1[f]=rsqrtf(q1-m1*m1+EPSV);
            g_m2[f]=m2; g_s2[f]=rsqrtf(q2-m2*m2+EPSV);
        }
    }
    gridsync(TAILBLK);

    // ---- D: per-block W1p (smem) + parallel bias c + A,B projections ----
    {
        float* sWp = (float*)sm_;                 // 6400 floats
        float* ssc = sWp + 6400;                  // 200
        float* ssh = ssc + 200;                   // 200
        float* spart = ssh + 200;                 // 512
        float* scc = spart + 512;                 // 32
        float (*srow)[100]    = (float(*)[100])(scc + 32);          // 800
        float (*spa)[2][32]   = (float(*)[2][32])(scc + 32 + 800);  // 512
        float (*spb)[2][32]   = (float(*)[2][32])(scc + 32 + 1312); // 512

        if (tid < 200){
            float m  = (tid<100)? __ldcg(&g_m1[tid]) : __ldcg(&g_m2[tid-100]);
            float sv = (tid<100)? __ldcg(&g_s1[tid]) : __ldcg(&g_s2[tid-100]);
            float sc = lbng[tid]*sv;
            ssc[tid] = sc;
            ssh[tid] = lbnb[tid]-m*sc;
        }
        __syncthreads();
        for(int t=tid;t<6400;t+=512){
            int o=t&31, f=t>>5;
            sWp[t] = lw1[o*200+f]*ssc[f];
        }
        {   // bias partials: 16 chunks x 32 outputs
            int o = tid&31, ch = tid>>5;
            int f0 = ch*12 + min(ch,8);
            int len = (ch<8)? 13 : 12;
            float acc=0.f;
            for(int u=0;u<len;u++){
                int f=f0+u;
                acc += lw1[o*200+f]*ssh[f];
            }
            spart[ch*32+o]=acc;
        }
        __syncthreads();
        if (tid<32){
            float c=lb1[tid];
#pragma unroll
            for(int ch=0;ch<16;ch++) c += spart[ch*32+tid];
            scc[tid]=c;
        }
        // node rows
        for(int t=tid;t<288;t+=512) srow[t/36][t%36]      = g_x [bid*8*36 + t];
        for(int t=tid;t<256;t+=512) srow[t>>5][36+(t&31)] = g_e1[bid*8*32 + t];
        for(int t=tid;t<256;t+=512) srow[t>>5][68+(t&31)] = g_e2[bid*8*32 + t];
        __syncthreads();
        float a=0.f, b=0.f;
        for(int u=0;u<50;u++){
            int f = 50*h+u;
            float v=srow[n8][f];
            a += v*sWp[f*32+lane];
            b += v*sWp[(100+f)*32+lane];
        }
        spa[n8][h][lane]=a; spb[n8][h][lane]=b;
        __syncthreads();
        if (h==0){
            g_A[node*32+lane]=spa[n8][0][lane]+spa[n8][1][lane]+scc[lane];
            g_B[node*32+lane]=spb[n8][0][lane]+spb[n8][1][lane];
        }
    }
}

// =====================================================================
// Pair kernel (unchanged from R6): SMEM staging + tf32 tensor cores
// =====================================================================
#define H1STRIDE 40
__global__ void __launch_bounds__(256,2) k_pairs_tc(
        const float* __restrict__ lw2, const float* __restrict__ lb2,
        const float* __restrict__ lw3, const float* __restrict__ lb3,
        float* __restrict__ out){
    __shared__ float sh1s[8][16*H1STRIDE];
    __shared__ float sW3[64], sB2[32], sB3[2];
    const int warp = threadIdx.x>>5, lane = threadIdx.x&31;
    const int g = lane>>2, tig = lane&3;

    if (threadIdx.x<64) sW3[threadIdx.x]=lw3[threadIdx.x];
    if (threadIdx.x<32) sB2[threadIdx.x]=lb2[threadIdx.x];
    if (threadIdx.x<2)  sB3[threadIdx.x]=lb3[threadIdx.x];
    __syncthreads();

    uint32_t Bhi[4][4][2], Blo[4][4][2];
#pragma unroll
    for(int s=0;s<4;s++){
#pragma unroll
        for(int nt=0;nt<4;nt++){
            int o = nt*8 + g;
#pragma unroll
            for(int h=0;h<2;h++){
                float wv = __ldg(&lw2[o*32 + s*8 + tig + 4*h]);
                uint32_t hi = to_tf32(wv);
                Bhi[s][nt][h] = hi;
                Blo[s][nt][h] = to_tf32(wv - __uint_as_float(hi));
            }
        }
    }

    float* sh = sh1s[warp];
    const int pr = lane>>1, half = lane&1;
    const int tile0 = (blockIdx.x*8 + warp)*4;

#pragma unroll 1
    for(int tt=0; tt<4; tt++){
        const int base = (tile0+tt)*16;
        {
            int p = base + pr;
            int disc=(2*NN-1)*(2*NN-1)-8*p;
            float sqv=sqrtf((float)disc);
            int i=(int)(((float)(2*NN-1)-sqv)*0.5f);
            if(i<0)i=0; if(i>NN-2)i=NN-2;
            while(i<NN-2 && rowstart(i+1)<=p) i++;
            while(i>0 && rowstart(i)>p) i--;
            int j = p-rowstart(i)+i+1;
            const float4* a4 = (const float4*)(g_A + i*32 + half*16);
            const float4* b4 = (const float4*)(g_B + j*32 + half*16);
            float4* row = (float4*)(sh + pr*H1STRIDE + half*16);
#pragma unroll
            for(int q=0;q<4;q++){
                float4 av=a4[q], bv=b4[q];
                float4 hv;
                hv.x=leaky(av.x+bv.x); hv.y=leaky(av.y+bv.y);
                hv.z=leaky(av.z+bv.z); hv.w=leaky(av.w+bv.w);
                row[q]=hv;
            }
        }
        __syncwarp();

        float C[4][4];
#pragma unroll
        for(int nt=0;nt<4;nt++){
            float c0=sB2[nt*8+2*tig], c1=sB2[nt*8+2*tig+1];
            C[nt][0]=c0; C[nt][1]=c1; C[nt][2]=c0; C[nt][3]=c1;
        }
#pragma unroll
        for(int s=0;s<4;s++){
            const int f0=s*8+tig, f1=f0+4;
            float v0 = sh[ g   *H1STRIDE + f0];
            float v1 = sh[(g+8)*H1STRIDE + f0];
            float v2 = sh[ g   *H1STRIDE + f1];
            float v3 = sh[(g+8)*H1STRIDE + f1];
            uint32_t Ah[4], Al[4];
            Ah[0]=to_tf32(v0); Al[0]=to_tf32(v0-__uint_as_float(Ah[0]));
            Ah[1]=to_tf32(v1); Al[1]=to_tf32(v1-__uint_as_float(Ah[1]));
            Ah[2]=to_tf32(v2); Al[2]=to_tf32(v2-__uint_as_float(Ah[2]));
            Ah[3]=to_tf32(v3); Al[3]=to_tf32(v3-__uint_as_float(Ah[3]));
#pragma unroll
            for(int nt=0;nt<4;nt++){
                mma_tf32(C[nt], Ah, Bhi[s][nt]);
                mma_tf32(C[nt], Ah, Blo[s][nt]);
                mma_tf32(C[nt], Al, Bhi[s][nt]);
            }
        }

        float y00=0.f,y01=0.f,y10=0.f,y11=0.f;
#pragma unroll
        for(int nt=0;nt<4;nt++){
            float w300=sW3[nt*8+2*tig],    w301=sW3[nt*8+2*tig+1];
            float w310=sW3[32+nt*8+2*tig], w311=sW3[32+nt*8+2*tig+1];
            float h0=leaky(C[nt][0]), h1v=leaky(C[nt][1]);
            float h2=leaky(C[nt][2]), h3=leaky(C[nt][3]);
            y00 += h0*w300 + h1v*w301;
            y01 += h0*w310 + h1v*w311;
            y10 += h2*w300 + h3*w301;
            y11 += h2*w310 + h3*w311;
        }
        y00 += __shfl_xor_sync(0xffffffffu,y00,1); y00 += __shfl_xor_sync(0xffffffffu,y00,2);
        y01 += __shfl_xor_sync(0xffffffffu,y01,1); y01 += __shfl_xor_sync(0xffffffffu,y01,2);
        y10 += __shfl_xor_sync(0xffffffffu,y10,1); y10 += __shfl_xor_sync(0xffffffffu,y10,2);
        y11 += __shfl_xor_sync(0xffffffffu,y11,1); y11 += __shfl_xor_sync(0xffffffffu,y11,2);
        if (tig==0){
            *(float2*)(out + (size_t)(base+g)*2)   = make_float2(y00+sB3[0], y01+sB3[1]);
            *(float2*)(out + (size_t)(base+g+8)*2) = make_float2(y10+sB3[0], y11+sB3[1]);
        }
        __syncwarp();
    }
}

// ---------------- launch: 5 kernels (capture #4 = k_tail2) ----------------
extern "C" void kernel_launch(void* const* d_in, const int* in_sizes, int n_in,
                              void* d_out, int out_size){
    const float* feat   = (const float*)d_in[0];
    const float* bn_g   = (const float*)d_in[1];
    const float* bn_b   = (const float*)d_in[2];
    const float* ec1_w1 = (const float*)d_in[3];
    const float* ec1_b1 = (const float*)d_in[4];
    const float* ec1_w2 = (const float*)d_in[5];
    const float* ec1_b2 = (const float*)d_in[6];
    const float* ec2_w1 = (const float*)d_in[7];
    const float* ec2_b1 = (const float*)d_in[8];
    const float* ec2_w2 = (const float*)d_in[9];
    const float* ec2_b2 = (const float*)d_in[10];
    const float* lbn_g  = (const float*)d_in[11];
    const float* lbn_b  = (const float*)d_in[12];
    const float* l_w1   = (const float*)d_in[13];
    const float* l_b1   = (const float*)d_in[14];
    const float* l_w2   = (const float*)d_in[15];
    const float* l_b2   = (const float*)d_in[16];
    const float* l_w3   = (const float*)d_in[17];
    const float* l_b3   = (const float*)d_in[18];
    float* out = (float*)d_out;

    static int attr_done = 0;
    if (!attr_done){
        cudaFuncSetAttribute(k_knn_e1, cudaFuncAttributeMaxDynamicSharedMemorySize, 49152);
        cudaFuncSetAttribute(k_tail2,  cudaFuncAttributeMaxDynamicSharedMemorySize, 45056);
        attr_done = 1;
    }

    k_stats <<<72, 512>>>(feat, ec1_w1, ec2_w1);
    k_norm  <<<72, 512>>>(feat, bn_g, bn_b, out + (size_t)2*NPAIR);
    k_knn_e1<<<128, 512, 49152>>>(ec1_b1, ec1_w2, ec1_b2);
    k_tail2 <<<TAILBLK, 512, 45056>>>(ec2_b1, ec2_w2, ec2_b2, l_w1, l_b1, lbn_g, lbn_b);
    k_pairs_tc<<<1023, 256>>>(l_w2, l_b2, l_w3, l_b3, out);
}

// round 8
// speedup vs baseline: 1.8660x; 1.0801x over previous
#include <cuda_runtime.h>
#include <math.h>
#include <stdint.h>

#define NN      1024
#define KNN     8
#define D_IN    36
#define NPAIR   (NN*(NN-1)/2)    // 523776
#define EPSV    1e-5f
#define SLOPE   0.01f

// ---------------- device scratch ----------------
__device__ float g_x[NN*36];              // normalized features
__device__ float g_e1[NN*32];             // edge conv 1 out
__device__ float g_e2[NN*32];             // edge conv 2 out
__device__ float g_mean[D_IN], g_scale[D_IN];
__device__ float4 g_xy[NN];
__device__ int   g_idx[NN*KNN];
__device__ float4 g_w1t1[72*32];          // ec1_w1 packed: [tt][o]
__device__ float4 g_w1t2[64*32];
__device__ float g_part[4*100*128];       // 2-stage pair-stats partials
__device__ float g_m1[100], g_s1[100], g_m2[100], g_s2[100];
__device__ float g_A[NN*32];
__device__ float g_B[NN*32];

__device__ __forceinline__ float leaky(float x){ return fmaxf(x, SLOPE*x); }
__device__ __forceinline__ int rowstart(int i){ return i*NN - ((i*(i+1))>>1); }

// tf32 helpers
__device__ __forceinline__ uint32_t to_tf32(float v){
    uint32_t r; asm("cvt.rna.tf32.f32 %0,%1;":"=r"(r):"f"(v)); return r;
}
__device__ __forceinline__ void mma_tf32(float* C, const uint32_t* A, const uint32_t* B){
    asm volatile(
      "mma.sync.aligned.m16n8k8.row.col.f32.tf32.tf32.f32 "
      "{%0,%1,%2,%3},{%4,%5,%6,%7},{%8,%9},{%0,%1,%2,%3};"
      : "+f"(C[0]),"+f"(C[1]),"+f"(C[2]),"+f"(C[3])
      : "r"(A[0]),"r"(A[1]),"r"(A[2]),"r"(A[3]),"r"(B[0]),"r"(B[1]));
}

// ============ k1: BN stats (blocks 0..35) + weight pack (36..71) ============
__global__ void __launch_bounds__(512) k_stats(const float* __restrict__ feat,
        const float* __restrict__ e1w1, const float* __restrict__ e2w1){
    __shared__ float ss[512], sq[512];
    int tid=threadIdx.x, bid=blockIdx.x;
    if (bid < 36){
        int f = bid;
        float s=0.f, q=0.f;
        for(int i=tid;i<NN;i+=512){ float v=feat[i*D_IN+f]; s+=v; q+=v*v; }
        ss[tid]=s; sq[tid]=q; __syncthreads();
        for(int o=256;o>0;o>>=1){
            if(tid<o){ ss[tid]+=ss[tid+o]; sq[tid]+=sq[tid+o]; }
            __syncthreads();
        }
        if(tid==0){
            float m=ss[0]*(1.f/NN);
            float var=sq[0]*(1.f/NN)-m*m;
            g_mean[f]=m; g_scale[f]=rsqrtf(var+EPSV);
        }
    } else {
        int t = (bid-36)*512 + tid;
        if (t < 72*32){ int tt=t>>5, o=t&31; g_w1t1[t] = *(const float4*)(e1w1 + o*288 + 4*tt); }
        if (t < 64*32){ int tt=t>>5, o=t&31; g_w1t2[t] = *(const float4*)(e2w1 + o*256 + 4*tt); }
    }
}

// ============ k2: normalize + cells + compact coords (72 x 512) ============
__global__ void __launch_bounds__(512) k_norm(const float* __restrict__ feat,
        const float* __restrict__ bng, const float* __restrict__ bnb,
        float* __restrict__ out_cells){
    int t = blockIdx.x*512 + threadIdx.x;
    int i=t/D_IN, f=t%D_IN;
    float v = (feat[t]-g_mean[f])*g_scale[f]*bng[f]+bnb[f];
    g_x[i*D_IN+f] = v;
    if (f < 4) ((float*)g_xy)[i*4+f] = v;
    if (t < NN*5){
        int ii=t/5, c=t%5;
        out_cells[ii*5+c] = feat[ii*D_IN+c];
    }
}

// ============ k3: kNN + edge conv 1 fused (128 x 512) ============
__global__ void __launch_bounds__(512) k_knn_e1(const float* __restrict__ b1,
        const float* __restrict__ w2, const float* __restrict__ b2){
    extern __shared__ char sm_[];
    const int tid=threadIdx.x, bid=blockIdx.x;
    const int w=tid>>5, lane=tid&31;
    const int n8=w>>1, h=w&1;
    const int node = bid*8 + n8;

    // ---- kNN (2 warps per node) ----
    {
        float4* sxy = (float4*)sm_;
        float  (*skd)[2][8] = (float(*)[2][8])(sm_+16384);
        int    (*ski)[2][8] = (int  (*)[2][8])(sm_+16896);
        for(int t=tid;t<NN;t+=512) sxy[t] = g_xy[t];
        __syncthreads();
        const float4 xi = sxy[node];
        float d8[8]; int id8[8];
#pragma unroll
        for(int k=0;k<8;k++){ d8[k]=3.4e38f; id8[k]=0x7fffffff; }
        float kth = 3.4e38f; int kthi = 0x7fffffff;
        for(int it=0; it<16; it++){
            int j = 512*h + it*32 + lane;
            float4 xj = sxy[j];
            float cd = fabsf(xi.x-xj.x)+fabsf(xi.y-xj.y)+fabsf(xi.z-xj.z)+fabsf(xi.w-xj.w);
            int ci = j;
            if (cd < kth || (cd==kth && ci < kthi)){
#pragma unroll
                for(int k=0;k<8;k++){
                    bool sw = (cd < d8[k]) || (cd==d8[k] && ci < id8[k]);
                    float td = sw ? d8[k] : cd; int ti = sw ? id8[k] : ci;
                    d8[k]  = sw ? cd : d8[k]; id8[k] = sw ? ci : id8[k];
                    cd=td; ci=ti;
                }
                kth = d8[7]; kthi = id8[7];
            }
        }
        for(int r=0;r<8;r++){
            float bd=d8[0]; int bi=id8[0];
#pragma unroll
            for(int off=16;off>0;off>>=1){
                float od=__shfl_xor_sync(0xffffffffu,bd,off);
                int   oi=__shfl_xor_sync(0xffffffffu,bi,off);
                if (od<bd || (od==bd && oi<bi)){ bd=od; bi=oi; }
            }
            if (lane==0){ skd[n8][h][r]=bd; ski[n8][h][r]=bi; }
            if (id8[0]==bi){
#pragma unroll
                for(int k=0;k<7;k++){ d8[k]=d8[k+1]; id8[k]=id8[k+1]; }
                d8[7]=3.4e38f; id8[7]=0x7fffffff;
            }
        }
        __syncthreads();
        if (h==0){
            float md = 3.4e38f; int mi = 0x7fffffff;
            if (lane < 16){ md = skd[n8][lane>>3][lane&7]; mi = ski[n8][lane>>3][lane&7]; }
            for(int r=0;r<8;r++){
                float bd=md; int bi=mi;
#pragma unroll
                for(int off=16;off>0;off>>=1){
                    float od=__shfl_xor_sync(0xffffffffu,bd,off);
                    int   oi=__shfl_xor_sync(0xffffffffu,bi,off);
                    if (od<bd || (od==bd && oi<bi)){ bd=od; bi=oi; }
                }
                if (lane==0) g_idx[node*KNN+r]=bi;
                if (md==bd && mi==bi){ md=3.4e38f; mi=0x7fffffff; }
            }
        }
    }
    __syncthreads();

    // ---- edge conv 1 ----
    {
        float4* sW  = (float4*)sm_;
        float (*sv)[288]   = (float(*)[288])(sm_+36864);
        float (*sh2)[2][32]= (float(*)[2][32])(sm_+46080);
        float (*sh1)[32]   = (float(*)[32])(sm_+48128);
        for(int t=tid;t<72*32;t+=512) sW[t]=g_w1t1[t];
        for(int t=lane;t<144;t+=32){
            int f = 18*h + (t>>3), k = t&7;
            int nb = g_idx[node*KNN+k];
            sv[n8][f*8+k] = g_x[nb*D_IN+f];
        }
        __syncthreads();
        float a0=0.f,a1=0.f,a2=0.f,a3=0.f;
        const float4* vv4 = (const float4*)sv[n8];
#pragma unroll
        for(int u=0;u<36;u++){
            int tt = 36*h+u;
            float4 wv = sW[tt*32+lane];
            float4 vv = vv4[tt];
            a0+=wv.x*vv.x; a1+=wv.y*vv.y; a2+=wv.z*vv.z; a3+=wv.w*vv.w;
        }
        sh2[n8][h][lane]=((a0+a1)+(a2+a3));
        __syncthreads();
        if (h==0){
            float acc = sh2[n8][0][lane]+sh2[n8][1][lane]+b1[lane];
            sh1[n8][lane]=leaky(acc);
            __syncwarp();
            float acc2 = b2[lane];
            const float4* w2v = (const float4*)(w2 + lane*32);
#pragma unroll
            for(int q=0;q<8;q++){
                float4 wv=w2v[q];
                acc2 += wv.x*sh1[n8][4*q]+wv.y*sh1[n8][4*q+1]+wv.z*sh1[n8][4*q+2]+wv.w*sh1[n8][4*q+3];
            }
            g_e1[node*32+lane]=leaky(acc2);
        }
    }
}

// ============ k4: edge conv 2 + stats stage 1 (128 x 512) ============
__global__ void __launch_bounds__(512) k_e2s1(
        const float* __restrict__ b1, const float* __restrict__ w2,
        const float* __restrict__ b2){
    extern __shared__ char sm_[];
    const int tid=threadIdx.x, bid=blockIdx.x;
    const int w=tid>>5, lane=tid&31;
    const int n8=w>>1, h=w&1;
    const int node = bid*8 + n8;

    // ---- edge conv 2 ----
    {
        float4* sW  = (float4*)sm_;                         // 32768
        float (*sv)[256]   = (float(*)[256])(sm_+32768);    // 8192
        float (*sh2)[2][32]= (float(*)[2][32])(sm_+40960);  // 2048
        float (*sh1)[32]   = (float(*)[32])(sm_+43008);     // 1024
        for(int t=tid;t<64*32;t+=512) sW[t]=g_w1t2[t];
        for(int t=lane;t<128;t+=32){
            int f = 16*h + (t>>3), k = t&7;
            int nb = g_idx[node*KNN+k];
            sv[n8][f*8+k] = g_e1[nb*32+f];
        }
        __syncthreads();
        float a0=0.f,a1=0.f,a2=0.f,a3=0.f;
        const float4* vv4 = (const float4*)sv[n8];
#pragma unroll
        for(int u=0;u<32;u++){
            int tt = 32*h+u;
            float4 wv = sW[tt*32+lane];
            float4 vv = vv4[tt];
            a0+=wv.x*vv.x; a1+=wv.y*vv.y; a2+=wv.z*vv.z; a3+=wv.w*vv.w;
        }
        sh2[n8][h][lane]=((a0+a1)+(a2+a3));
        __syncthreads();
        if (h==0){
            float acc = sh2[n8][0][lane]+sh2[n8][1][lane]+b1[lane];
            sh1[n8][lane]=leaky(acc);
            __syncwarp();
            float acc2 = b2[lane];
            const float4* w2v = (const float4*)(w2 + lane*32);
#pragma unroll
            for(int q=0;q<8;q++){
                float4 wv=w2v[q];
                acc2 += wv.x*sh1[n8][4*q]+wv.y*sh1[n8][4*q+1]+wv.z*sh1[n8][4*q+2]+wv.w*sh1[n8][4*q+3];
            }
            g_e2[node*32+lane]=leaky(acc2);
        }
    }
    __syncthreads();

    // ---- stats stage 1: per-block (8 nodes) weighted partials ----
    {
        float (*srow)[100] = (float(*)[100])sm_;
        for(int t=tid;t<288;t+=512) srow[t/36][t%36]      = g_x [bid*8*36 + t];
        for(int t=tid;t<256;t+=512) srow[t>>5][36+(t&31)] = g_e1[bid*8*32 + t];
        __syncthreads();   // e2 already in smem-written g_e2? read from sh? simpler: read back
        for(int t=tid;t<256;t+=512) srow[t>>5][68+(t&31)] = g_e2[bid*8*32 + t];
        __syncthreads();
        if (tid < 400){
            int c = tid/100, f = tid%100;
            float acc=0.f;
#pragma unroll
            for(int nd=0;nd<8;nd++){
                int gi = bid*8+nd;
                float v = srow[nd][f];
                float wt = (c<2)? (float)(NN-1-gi) : (float)gi;
                float vv = (c&1)? v*v : v;
                acc += wt*vv;
            }
            g_part[(c*100+f)*128 + bid] = acc;
        }
    }
}

// ============ k5: stats stage 2 (100 x 512) ============
__global__ void __launch_bounds__(512) k_stats2(){
    __shared__ float red[512];
    const int tid=threadIdx.x, f=blockIdx.x;
    int c = tid>>7, idx = tid&127;
    red[tid] = g_part[(c*100+f)*128 + idx];
    __syncthreads();
    for(int o=64;o>0;o>>=1){
        if ((tid&127) < o) red[tid] += red[tid+o];
        __syncthreads();
    }
    if (tid==0){
        const float invP = 1.0f/(float)NPAIR;
        float m1=red[0]*invP,   q1=red[128]*invP;
        float m2=red[256]*invP, q2=red[384]*invP;
        g_m1[f]=m1; g_s1[f]=rsqrtf(q1-m1*m1+EPSV);
        g_m2[f]=m2; g_s2[f]=rsqrtf(q2-m2*m2+EPSV);
    }
}

// ============ k6: W1p + bias + A,B projections (128 x 512) ============
__global__ void __launch_bounds__(512) k_abk(
        const float* __restrict__ lw1, const float* __restrict__ lb1,
        const float* __restrict__ lbng, const float* __restrict__ lbnb){
    extern __shared__ char sm_[];
    const int tid=threadIdx.x, bid=blockIdx.x;
    const int w=tid>>5, lane=tid&31;
    const int n8=w>>1, h=w&1;
    const int node = bid*8 + n8;

    float* sWp = (float*)sm_;                 // 6400
    float* ssc = sWp + 6400;                  // 200
    float* ssh = ssc + 200;                   // 200
    float* spart = ssh + 200;                 // 512
    float* scc = spart + 512;                 // 32
    float (*srow)[100]  = (float(*)[100])(scc + 32);          // 800
    float (*spa)[2][32] = (float(*)[2][32])(scc + 32 + 800);  // 512
    float (*spb)[2][32] = (float(*)[2][32])(scc + 32 + 1312); // 512

    if (tid < 200){
        float m  = (tid<100)? g_m1[tid] : g_m2[tid-100];
        float sv = (tid<100)? g_s1[tid] : g_s2[tid-100];
        float sc = lbng[tid]*sv;
        ssc[tid] = sc;
        ssh[tid] = lbnb[tid]-m*sc;
    }
    __syncthreads();
    for(int t=tid;t<6400;t+=512){
        int o=t&31, f=t>>5;
        sWp[t] = lw1[o*200+f]*ssc[f];
    }
    {   // bias partials: 16 chunks x 32 outputs
        int o = tid&31, ch = tid>>5;
        int f0 = ch*12 + min(ch,8);
        int len = (ch<8)? 13 : 12;
        float acc=0.f;
        for(int u=0;u<len;u++){
            int f=f0+u;
            acc += lw1[o*200+f]*ssh[f];
        }
        spart[ch*32+o]=acc;
    }
    __syncthreads();
    if (tid<32){
        float c=lb1[tid];
#pragma unroll
        for(int ch=0;ch<16;ch++) c += spart[ch*32+tid];
        scc[tid]=c;
    }
    for(int t=tid;t<288;t+=512) srow[t/36][t%36]      = g_x [bid*8*36 + t];
    for(int t=tid;t<256;t+=512) srow[t>>5][36+(t&31)] = g_e1[bid*8*32 + t];
    for(int t=tid;t<256;t+=512) srow[t>>5][68+(t&31)] = g_e2[bid*8*32 + t];
    __syncthreads();
    float a=0.f, b=0.f;
    for(int u=0;u<50;u++){
        int f = 50*h+u;
        float v=srow[n8][f];
        a += v*sWp[f*32+lane];
        b += v*sWp[(100+f)*32+lane];
    }
    spa[n8][h][lane]=a; spb[n8][h][lane]=b;
    __syncthreads();
    if (h==0){
        g_A[node*32+lane]=spa[n8][0][lane]+spa[n8][1][lane]+scc[lane];
        g_B[node*32+lane]=spb[n8][0][lane]+spb[n8][1][lane];
    }
}

// =====================================================================
// Pair kernel: SMEM staging + tf32 MMA (2-term split, conflict-free LDS)
// =====================================================================
#define H1STRIDE 36
__global__ void __launch_bounds__(256,2) k_pairs_tc(
        const float* __restrict__ lw2, const float* __restrict__ lb2,
        const float* __restrict__ lw3, const float* __restrict__ lb3,
        float* __restrict__ out){
    __shared__ float sh1s[8][16*H1STRIDE];
    __shared__ float sW3[64], sB2[32], sB3[2];
    const int warp = threadIdx.x>>5, lane = threadIdx.x&31;
    const int g = lane>>2, tig = lane&3;

    if (threadIdx.x<64) sW3[threadIdx.x]=lw3[threadIdx.x];
    if (threadIdx.x<32) sB2[threadIdx.x]=lb2[threadIdx.x];
    if (threadIdx.x<2)  sB3[threadIdx.x]=lb3[threadIdx.x];
    __syncthreads();

    uint32_t Bhi[4][4][2], Blo[4][4][2];
#pragma unroll
    for(int s=0;s<4;s++){
#pragma unroll
        for(int nt=0;nt<4;nt++){
            int o = nt*8 + g;
#pragma unroll
            for(int h=0;h<2;h++){
                float wv = __ldg(&lw2[o*32 + s*8 + tig + 4*h]);
                uint32_t hi = to_tf32(wv);
                Bhi[s][nt][h] = hi;
                Blo[s][nt][h] = to_tf32(wv - __uint_as_float(hi));
            }
        }
    }

    float* sh = sh1s[warp];
    const int pr = lane>>1, half = lane&1;
    const int tile0 = (blockIdx.x*8 + warp)*4;

#pragma unroll 1
    for(int tt=0; tt<4; tt++){
        const int base = (tile0+tt)*16;
        {
            int p = base + pr;
            int disc=(2*NN-1)*(2*NN-1)-8*p;
            float sqv=sqrtf((float)disc);
            int i=(int)(((float)(2*NN-1)-sqv)*0.5f);
            if(i<0)i=0; if(i>NN-2)i=NN-2;
            while(i<NN-2 && rowstart(i+1)<=p) i++;
            while(i>0 && rowstart(i)>p) i--;
            int j = p-rowstart(i)+i+1;
            const float4* a4 = (const float4*)(g_A + i*32 + half*16);
            const float4* b4 = (const float4*)(g_B + j*32 + half*16);
            float4* row = (float4*)(sh + pr*H1STRIDE + half*16);
#pragma unroll
            for(int q=0;q<4;q++){
                float4 av=a4[q], bv=b4[q];
                float4 hv;
                hv.x=leaky(av.x+bv.x); hv.y=leaky(av.y+bv.y);
                hv.z=leaky(av.z+bv.z); hv.w=leaky(av.w+bv.w);
                row[q]=hv;
            }
        }
        __syncwarp();

        float C[4][4];
#pragma unroll
        for(int nt=0;nt<4;nt++){
            float c0=sB2[nt*8+2*tig], c1=sB2[nt*8+2*tig+1];
            C[nt][0]=c0; C[nt][1]=c1; C[nt][2]=c0; C[nt][3]=c1;
        }
#pragma unroll
        for(int s=0;s<4;s++){
            const int f0=s*8+tig, f1=f0+4;
            float v0 = sh[ g   *H1STRIDE + f0];
            float v1 = sh[(g+8)*H1STRIDE + f0];
            float v2 = sh[ g   *H1STRIDE + f1];
            float v3 = sh[(g+8)*H1STRIDE + f1];
            uint32_t Ah[4];
            Ah[0]=to_tf32(v0); Ah[1]=to_tf32(v1);
            Ah[2]=to_tf32(v2); Ah[3]=to_tf32(v3);
#pragma unroll
            for(int nt=0;nt<4;nt++){
                mma_tf32(C[nt], Ah, Bhi[s][nt]);
                mma_tf32(C[nt], Ah, Blo[s][nt]);
            }
        }

        float y00=0.f,y01=0.f,y10=0.f,y11=0.f;
#pragma unroll
        for(int nt=0;nt<4;nt++){
            float w300=sW3[nt*8+2*tig],    w301=sW3[nt*8+2*tig+1];
            float w310=sW3[32+nt*8+2*tig], w311=sW3[32+nt*8+2*tig+1];
            float h0=leaky(C[nt][0]), h1v=leaky(C[nt][1]);
            float h2=leaky(C[nt][2]), h3=leaky(C[nt][3]);
            y00 += h0*w300 + h1v*w301;
            y01 += h0*w310 + h1v*w311;
            y10 += h2*w300 + h3*w301;
            y11 += h2*w310 + h3*w311;
        }
        y00 += __shfl_xor_sync(0xffffffffu,y00,1); y00 += __shfl_xor_sync(0xffffffffu,y00,2);
        y01 += __shfl_xor_sync(0xffffffffu,y01,1); y01 += __shfl_xor_sync(0xffffffffu,y01,2);
        y10 += __shfl_xor_sync(0xffffffffu,y10,1); y10 += __shfl_xor_sync(0xffffffffu,y10,2);
        y11 += __shfl_xor_sync(0xffffffffu,y11,1); y11 += __shfl_xor_sync(0xffffffffu,y11,2);
        if (tig==0){
            *(float2*)(out + (size_t)(base+g)*2)   = make_float2(y00+sB3[0], y01+sB3[1]);
            *(float2*)(out + (size_t)(base+g+8)*2) = make_float2(y10+sB3[0], y11+sB3[1]);
        }
        __syncwarp();
    }
}

// ---------------- launch: 7 kernels ----------------
extern "C" void kernel_launch(void* const* d_in, const int* in_sizes, int n_in,
                              void* d_out, int out_size){
    const float* feat   = (const float*)d_in[0];
    const float* bn_g   = (const float*)d_in[1];
    const float* bn_b   = (const float*)d_in[2];
    const float* ec1_w1 = (const float*)d_in[3];
    const float* ec1_b1 = (const float*)d_in[4];
    const float* ec1_w2 = (const float*)d_in[5];
    const float* ec1_b2 = (const float*)d_in[6];
    const float* ec2_w1 = (const float*)d_in[7];
    const float* ec2_b1 = (const float*)d_in[8];
    const float* ec2_w2 = (const float*)d_in[9];
    const float* ec2_b2 = (const float*)d_in[10];
    const float* lbn_g  = (const float*)d_in[11];
    const float* lbn_b  = (const float*)d_in[12];
    const float* l_w1   = (const float*)d_in[13];
    const float* l_b1   = (const float*)d_in[14];
    const float* l_w2   = (const float*)d_in[15];
    const float* l_b2   = (const float*)d_in[16];
    const float* l_w3   = (const float*)d_in[17];
    const float* l_b3   = (const float*)d_in[18];
    float* out = (float*)d_out;

    static int attr_done = 0;
    if (!attr_done){
        cudaFuncSetAttribute(k_knn_e1, cudaFuncAttributeMaxDynamicSharedMemorySize, 49152);
        cudaFuncSetAttribute(k_e2s1,   cudaFuncAttributeMaxDynamicSharedMemorySize, 45056);
        cudaFuncSetAttribute(k_abk,    cudaFuncAttributeMaxDynamicSharedMemorySize, 36864);
        attr_done = 1;
    }

    k_stats  <<<72, 512>>>(feat, ec1_w1, ec2_w1);
    k_norm   <<<72, 512>>>(feat, bn_g, bn_b, out + (size_t)2*NPAIR);
    k_knn_e1 <<<128, 512, 49152>>>(ec1_b1, ec1_w2, ec1_b2);
    k_e2s1   <<<128, 512, 45056>>>(ec2_b1, ec2_w2, ec2_b2);
    k_stats2 <<<100, 512>>>();
    k_abk    <<<128, 512, 36864>>>(l_w1, l_b1, lbn_g, lbn_b);
    k_pairs_tc<<<1023, 256>>>(l_w2, l_b2, l_w3, l_b3, out);
}